// round 12
// baseline (speedup 1.0000x reference)
#include <cuda_runtime.h>

#define BB 64
#define PP 32768
#define GG 64

// ---------------- device scratch ----------------
__device__ int    g_cellv[PP];
__device__ int    g_chist[128 * 256];
__device__ float4 g_sppt[PP];     // sorted point-form priors
__device__ float  g_spar[PP];     // sorted areas
__device__ int    g_sidx[PP];     // sorted -> original index
__device__ float2 g_bt2[BB * PP]; // (best_truth_overlap, best_truth_idx-bits)
__device__ unsigned long long g_best[BB * GG];
__device__ float  g_lossc[BB * PP];
__device__ int    g_hist1[BB * 256];   // per-batch top-byte histogram
__device__ int    g_poslist[BB * PP];
__device__ int    g_segcnt[BB * 128];
__device__ int    g_numpos[BB];
__device__ int    g_anyvalid[BB];
__device__ double g_acc[3];
__device__ double g_topk;

__device__ __forceinline__ float sl1(float d) {
    float a = fabsf(d);
    return a < 1.0f ? 0.5f * d * d : a - 0.5f;
}

// ---------------- sort step 1 (+ fused global init) -------------------------
__global__ void __launch_bounds__(256) k_cell(const float* __restrict__ priors) {
    __shared__ int sh[256];
    int tid = threadIdx.x;
    int gt = blockIdx.x * 256 + tid;           // 0..32767
    // fused init
    if (gt < BB * GG) g_best[gt] = 0x00000000FFFFFFFFull;  // ratio=0, p=0
    if (gt < BB) g_numpos[gt] = 0;
    if (gt < 3) g_acc[gt] = 0.0;
    if (gt == 3) g_topk = 0.0;
    if (gt < BB * 256) g_hist1[gt] = 0;

    sh[tid] = 0;
    __syncthreads();
    float4 pr = ((const float4*)priors)[gt];
    int cx = min(7, max(0, (int)(pr.x * 8.0f)));
    int cy = min(7, max(0, (int)(pr.y * 8.0f)));
    float mwh = fmaxf(pr.z, pr.w);
    int sc = min(3, max(0, (int)((mwh - 0.02f) * 14.2857f)));
    int cell = ((cy * 8 + cx) << 2) | sc;
    g_cellv[gt] = cell;
    atomicAdd(&sh[cell], 1);
    __syncthreads();
    g_chist[blockIdx.x * 256 + tid] = sh[tid];
}

// ---------------- sort step 2: fused scan + rank-stable scatter -------------
__global__ void __launch_bounds__(256) k_ssort(const float* __restrict__ priors) {
    __shared__ int soff[256];
    __shared__ int sscan[256];
    __shared__ int scnt[8][256];
    int tid = threadIdx.x, lane = tid & 31, wid = tid >> 5;

    // per-cell totals + prefix of chunks before mine (hist is hot in L2)
    int mytot = 0, mypre = 0;
    int myck = blockIdx.x;
#pragma unroll 8
    for (int ch = 0; ch < 128; ch++) {
        int v = g_chist[ch * 256 + tid];
        mytot += v;
        if (ch < myck) mypre += v;
    }
    // block exclusive scan over cell totals
    sscan[tid] = mytot;
    __syncthreads();
    for (int off = 1; off < 256; off <<= 1) {
        int v = (tid >= off) ? sscan[tid - off] : 0;
        __syncthreads();
        sscan[tid] += v;
        __syncthreads();
    }
    soff[tid] = sscan[tid] - mytot + mypre;
#pragma unroll
    for (int i = 0; i < 8; i++) scnt[i][tid] = 0;
    __syncthreads();

    int p = blockIdx.x * 256 + tid;
    int cell = g_cellv[p];
    atomicAdd(&scnt[wid][cell], 1);
    unsigned mk = __match_any_sync(0xFFFFFFFFu, cell);
    int rank = __popc(mk & ((1u << lane) - 1));
    __syncthreads();
    int before = 0;
    for (int w = 0; w < wid; w++) before += scnt[w][cell];
    int slot = soff[cell] + before + rank;

    float4 pr = ((const float4*)priors)[p];
    float4 pt = make_float4(pr.x - pr.z * 0.5f, pr.y - pr.w * 0.5f,
                            pr.x + pr.z * 0.5f, pr.y + pr.w * 0.5f);
    g_sppt[slot] = pt;
    g_spar[slot] = (pt.z - pt.x) * (pt.w - pt.y);
    g_sidx[slot] = p;
}

// ---------------- fused match: one culled pass ----------------
__global__ void __launch_bounds__(256, 5) k_match(const float* __restrict__ targets) {
    __shared__ float sgx1[GG], sgy1[GG], sgx2[GG], sgy2[GG], sga[GG];
    __shared__ float s_r[8][GG];
    __shared__ int   s_ix[8][GG];

    int b = blockIdx.y, tid = threadIdx.x;
    int lane = tid & 31, wid = tid >> 5;

    if (tid < GG) {
        const float* t = targets + ((size_t)b * GG + tid) * 15;
        float x1 = t[0], y1 = t[1], x2 = t[2], y2 = t[3];
        sgx1[tid] = x1; sgy1[tid] = y1; sgx2[tid] = x2; sgy2[tid] = y2;
        sga[tid] = (x2 - x1) * (y2 - y1);
    }
    for (int i = tid; i < 8 * GG; i += 256) {
        ((float*)s_r)[i] = 0.0f;
        ((int*)s_ix)[i] = 0x7FFFFFFF;
    }
    __syncthreads();

    int s0 = blockIdx.x * 1024 + wid * 128 + lane;
    float4 q[4]; float qa[4]; int qi[4];
#pragma unroll
    for (int k = 0; k < 4; k++) {
        q[k] = g_sppt[s0 + 32 * k];
        qa[k] = g_spar[s0 + 32 * k];
        qi[k] = g_sidx[s0 + 32 * k];
    }
    // warp bbox over its 128 priors
    float bx1 = q[0].x, by1 = q[0].y, bx2 = q[0].z, by2 = q[0].w;
#pragma unroll
    for (int k = 1; k < 4; k++) {
        bx1 = fminf(bx1, q[k].x); by1 = fminf(by1, q[k].y);
        bx2 = fmaxf(bx2, q[k].z); by2 = fmaxf(by2, q[k].w);
    }
#pragma unroll
    for (int off = 16; off > 0; off >>= 1) {
        bx1 = fminf(bx1, __shfl_xor_sync(0xFFFFFFFFu, bx1, off));
        by1 = fminf(by1, __shfl_xor_sync(0xFFFFFFFFu, by1, off));
        bx2 = fmaxf(bx2, __shfl_xor_sync(0xFFFFFFFFu, bx2, off));
        by2 = fmaxf(by2, __shfl_xor_sync(0xFFFFFFFFu, by2, off));
    }

    // 64-bit GT hit mask
    bool h0 = sgx1[lane] < bx2 && sgx2[lane] > bx1 &&
              sgy1[lane] < by2 && sgy2[lane] > by1;
    bool h1 = sgx1[lane + 32] < bx2 && sgx2[lane + 32] > bx1 &&
              sgy1[lane + 32] < by2 && sgy2[lane + 32] > by1;
    unsigned m0 = __ballot_sync(0xFFFFFFFFu, h0);
    unsigned m1 = __ballot_sync(0xFFFFFFFFu, h1);
    unsigned long long mask =
        (unsigned long long)m0 | ((unsigned long long)m1 << 32);

    float bin[4], bun[4]; int bix[4];
#pragma unroll
    for (int k = 0; k < 4; k++) { bin[k] = 0.0f; bun[k] = 1.0f; bix[k] = 0; }

    while (mask) {
        int g = __ffsll((long long)mask) - 1;
        mask &= mask - 1;
        float x1 = sgx1[g], y1 = sgy1[g], x2 = sgx2[g], y2 = sgy2[g];
        float ar = sga[g];
        float ti[4], tu[4];
#pragma unroll
        for (int k = 0; k < 4; k++) {
            float lx = fmaxf(x1, q[k].x), ly = fmaxf(y1, q[k].y);
            float rx = fminf(x2, q[k].z), ry = fminf(y2, q[k].w);
            float w = fmaxf(rx - lx, 0.0f), h = fmaxf(ry - ly, 0.0f);
            float inter = w * h;
            float un = (ar + qa[k]) - inter;
            ti[k] = inter; tu[k] = un;
            if (inter * bun[k] > bin[k] * un) { bin[k] = inter; bun[k] = un; bix[k] = g; }
        }
        // local 4-way merge (cross-mult, keep-self on tie)
        float ri = ti[0], ru = tu[0]; int rp = qi[0];
#pragma unroll
        for (int k = 1; k < 4; k++)
            if (ti[k] * ru > ri * tu[k]) { ri = ti[k]; ru = tu[k]; rp = qi[k]; }
        // collapse to ratio; REDUX-based warp argmax
        float r = __fdividef(ri, ru);
        unsigned rb = __float_as_uint(r);          // r >= 0: bits monotone
        unsigned rmax = __reduce_max_sync(0xFFFFFFFFu, rb);
        if (rmax != 0u) {
            unsigned who = __ballot_sync(0xFFFFFFFFu, rb == rmax);
            int src = __ffs(who) - 1;
            int wp = __shfl_sync(0xFFFFFFFFu, rp, src);
            if (lane == 0) {
                s_r[wid][g] = __uint_as_float(rmax);
                s_ix[wid][g] = wp;
            }
        }
    }

    // per-prior results (scatter to original index; 8B stores)
#pragma unroll
    for (int k = 0; k < 4; k++)
        g_bt2[(size_t)b * PP + qi[k]] =
            make_float2(bin[k] / bun[k], __int_as_float(bix[k]));

    __syncthreads();
    // block merge per g + global atomic merge
    if (tid < GG) {
        float r = s_r[0][tid]; int rp = s_ix[0][tid];
#pragma unroll
        for (int w = 1; w < 8; w++) {
            float orr = s_r[w][tid]; int op = s_ix[w][tid];
            if (orr > r || (orr == r && op < rp)) { r = orr; rp = op; }
        }
        if (rp != 0x7FFFFFFF) {
            unsigned long long key =
                ((unsigned long long)__float_as_uint(r) << 32) |
                (unsigned)(~(unsigned)rp);
            atomicMax(&g_best[b * GG + tid], key);
        }
    }
}

// ---------------- parallel scatter corrections ----------------
__global__ void __launch_bounds__(64) k_scatter() {
    int b = blockIdx.x;
    int g = threadIdx.x;
    __shared__ int sp[GG];
    __shared__ int sany;
    if (g == 0) sany = 0;

    unsigned long long key = g_best[b * GG + g];
    int p = (int)(~(unsigned)(key & 0xFFFFFFFFull));
    float ratio = __uint_as_float((unsigned)(key >> 32));
    bool valid = ratio >= 0.2f;
    sp[g] = p;
    __syncthreads();

    if (valid) {
        sany = 1;
        g_bt2[(size_t)b * PP + p].x = 2.0f;
    }
    bool write = true;
    for (int g2 = g + 1; g2 < GG; g2++)
        if (sp[g2] == p) { write = false; break; }
    if (write) g_bt2[(size_t)b * PP + p].y = __int_as_float(g);

    __syncthreads();
    if (g == 0) g_anyvalid[b] = sany;
}

// ---------------- slim per-prior loss_c + pos compaction + hist pass 1 -----
__global__ void __launch_bounds__(256) k_losses(const float* __restrict__ conf_data,
                                                const float* __restrict__ targets) {
    __shared__ int swc[8];
    __shared__ int shist[256];
    int b = blockIdx.y, tid = threadIdx.x;
    int lane = tid & 31, wid = tid >> 5;
    shist[tid] = 0;

    int p = blockIdx.x * 256 + tid;
    size_t o = (size_t)b * PP + p;
    float2 bt = g_bt2[o];
    float ov = bt.x;
    int g = __float_as_int(bt.y);
    int av = g_anyvalid[b];

    int conf = 0;
    if (av && ov >= 0.35f)
        conf = (int)__ldg(&targets[((size_t)b * GG + g) * 15 + 14]);

    const float* cd = conf_data + o * 3;
    float c0 = cd[0], c1 = cd[1], c2 = cd[2];
    float mx = fmaxf(c0, fmaxf(c1, c2));
    float lse = mx + __logf(__expf(c0 - mx) + __expf(c1 - mx) + __expf(c2 - mx));
    float gathered = (conf == 0) ? c0 : ((conf == 1) ? c1 : c2);
    float lcv = lse - gathered;
    bool pos = conf > 0;
    float stored = pos ? 0.0f : lcv;
    g_lossc[o] = stored;

    unsigned m = __ballot_sync(0xFFFFFFFFu, pos);
    if (lane == 0) swc[wid] = __popc(m);
    __syncthreads();

    atomicAdd(&shist[__float_as_uint(stored) >> 24], 1);

    int base = 0;
#pragma unroll
    for (int w = 0; w < 8; w++)
        if (w < wid) base += swc[w];
    if (pos)
        g_poslist[((size_t)b * 128 + blockIdx.x) * 256 + base +
                  __popc(m & ((1u << lane) - 1))] = p;
    __syncthreads();

    if (shist[tid]) atomicAdd(&g_hist1[b * 256 + tid], shist[tid]);
    if (tid == 0) {
        int c = 0;
#pragma unroll
        for (int w = 0; w < 8; w++) c += swc[w];
        g_segcnt[b * 128 + blockIdx.x] = c;
        if (c) atomicAdd(&g_numpos[b], c);
    }
}

// ---------------- fused tail: blocks 0-63 topk, blocks 64-319 pos ----------
#define TKT 1024
__global__ void __launch_bounds__(TKT) k_tail(const float* __restrict__ loc_data,
                                              const float* __restrict__ conf_data,
                                              const float* __restrict__ landm_data,
                                              const float* __restrict__ priors,
                                              const float* __restrict__ targets) {
    int tid = threadIdx.x, lane = tid & 31, wid = tid >> 5;

    if (blockIdx.x >= 64) {
        // ---- pos path: one segment per warp ----
        int seg = (blockIdx.x - 64) * 32 + wid;
        int cnt = g_segcnt[seg];
        int b = seg >> 7;
        size_t segbase = (size_t)seg * 256;
        double dl = 0.0, dlm = 0.0, dcp = 0.0;
        for (int i = lane; i < cnt; i += 32) {
            int p = g_poslist[segbase + i];
            size_t o = (size_t)b * PP + p;
            int g = __float_as_int(g_bt2[o].y);
            const float* t = targets + ((size_t)b * GG + g) * 15;
            int conf = (int)t[14];

            const float* cd = conf_data + o * 3;
            float c0 = cd[0], c1 = cd[1], c2 = cd[2];
            float mx = fmaxf(c0, fmaxf(c1, c2));
            float lse = mx + __logf(__expf(c0 - mx) + __expf(c1 - mx) + __expf(c2 - mx));
            dcp += (double)(lse - ((conf == 1) ? c1 : c2));

            float4 pr = ((const float4*)priors)[p];
            float dwx = 0.1f * pr.z, dwy = 0.1f * pr.w;
            float m0 = t[0], m1 = t[1], m2 = t[2], m3 = t[3];
            float gcx = ((m0 + m2) * 0.5f - pr.x) / dwx;
            float gcy = ((m1 + m3) * 0.5f - pr.y) / dwy;
            float gw2 = __logf((m2 - m0) / pr.z) * 5.0f;
            float gh2 = __logf((m3 - m1) / pr.w) * 5.0f;
            const float* ld = loc_data + o * 4;
            dl += (double)(sl1(ld[0] - gcx) + sl1(ld[1] - gcy) +
                           sl1(ld[2] - gw2) + sl1(ld[3] - gh2));

            const float* lt = t + 4;
            const float* lm = landm_data + o * 10;
            int nd = (conf == 1) ? 10 : 4;
            float s = 0.0f;
            for (int j = 0; j < nd; j += 2) {
                float lx = (lt[j] - pr.x) / dwx;
                float ly = (lt[j + 1] - pr.y) / dwy;
                s += sl1(lm[j] - lx) + sl1(lm[j + 1] - ly);
            }
            dlm += (double)s;
        }
#pragma unroll
        for (int off = 16; off > 0; off >>= 1) {
            dl  += __shfl_down_sync(0xFFFFFFFFu, dl, off);
            dlm += __shfl_down_sync(0xFFFFFFFFu, dlm, off);
            dcp += __shfl_down_sync(0xFFFFFFFFu, dcp, off);
        }
        __shared__ double sdp[3][32];
        if (lane == 0) { sdp[0][wid] = dl; sdp[1][wid] = dlm; sdp[2][wid] = dcp; }
        __syncthreads();
        if (tid == 0) {
            double a = 0, b2 = 0, c = 0;
#pragma unroll
            for (int w = 0; w < 32; w++) { a += sdp[0][w]; b2 += sdp[1][w]; c += sdp[2][w]; }
            if (a != 0.0 || b2 != 0.0 || c != 0.0) {
                atomicAdd(&g_acc[0], a);
                atomicAdd(&g_acc[1], b2);
                atomicAdd(&g_acc[2], c);
            }
        }
        return;
    }

    // ---- topk path ----
    int b = blockIdx.x;
    int np = g_numpos[b];
    long long kk = 7LL * np;
    if (kk > PP - 1) kk = PP - 1;
    if (kk <= 0) return;
    int k = (int)kk;

    const float* v = g_lossc + (size_t)b * PP;

    __shared__ int shist[4096];
    __shared__ int swtot[32];
    __shared__ unsigned s_prefix;
    __shared__ int s_krem;

    int krem = k;
    unsigned prefix;

    // ---- pass 1: top byte from precomputed g_hist1 ----
    {
        int cnt = (tid < 256) ? g_hist1[b * 256 + tid] : 0;
        int s = cnt;
#pragma unroll
        for (int off = 1; off < 32; off <<= 1) {
            int o2 = __shfl_down_sync(0xFFFFFFFFu, s, off);
            if (lane + off < 32) s += o2;
        }
        if (lane == 0) swtot[wid] = s;
        __syncthreads();
        if (tid < 256) {
            int above = 0;
#pragma unroll
            for (int w = 0; w < 8; w++)
                if (w > wid) above += swtot[w];
            int suffix = s + above;
            if (suffix >= krem && suffix - cnt < krem) {
                s_prefix = (unsigned)tid << 24;
                s_krem = krem - (suffix - cnt);
            }
        }
        __syncthreads();
        prefix = s_prefix;
        krem = s_krem;
        __syncthreads();
    }

    // ---- pass 2: bits 23..12 ----
    for (int i = tid; i < 4096; i += TKT) shist[i] = 0;
    __syncthreads();
#pragma unroll 4
    for (int i = tid; i < PP; i += TKT) {
        unsigned u = __float_as_uint(v[i]);
        if ((u & 0xFF000000u) == prefix)
            atomicAdd(&shist[(u >> 12) & 0xFFFu], 1);
    }
    __syncthreads();
    {
        int b0 = tid * 4;
        int c0 = shist[b0], c1 = shist[b0 + 1], c2 = shist[b0 + 2], c3 = shist[b0 + 3];
        int cnt = c0 + c1 + c2 + c3;
        int s = cnt;
#pragma unroll
        for (int off = 1; off < 32; off <<= 1) {
            int o2 = __shfl_down_sync(0xFFFFFFFFu, s, off);
            if (lane + off < 32) s += o2;
        }
        if (lane == 0) swtot[wid] = s;
        __syncthreads();
        int above = 0;
#pragma unroll
        for (int w = 0; w < 32; w++)
            if (w > wid) above += swtot[w];
        int suffix = s + above;
        int cum = suffix - cnt;
        if (cum < krem && suffix >= krem) {
            int bin, c;
            if (cum + c3 >= krem)                { bin = b0 + 3; c = cum; }
            else if (cum + c3 + c2 >= krem)      { bin = b0 + 2; c = cum + c3; }
            else if (cum + c3 + c2 + c1 >= krem) { bin = b0 + 1; c = cum + c3 + c2; }
            else                                 { bin = b0;     c = cum + c3 + c2 + c1; }
            s_prefix = prefix | ((unsigned)bin << 12);
            s_krem = krem - c;
        }
        __syncthreads();
        prefix = s_prefix;
        krem = s_krem;
        __syncthreads();
    }

    // ---- pass 3: bits 11..0 ----
    for (int i = tid; i < 4096; i += TKT) shist[i] = 0;
    __syncthreads();
#pragma unroll 4
    for (int i = tid; i < PP; i += TKT) {
        unsigned u = __float_as_uint(v[i]);
        if ((u & 0xFFFFF000u) == prefix)
            atomicAdd(&shist[u & 0xFFFu], 1);
    }
    __syncthreads();
    {
        int b0 = tid * 4;
        int c0 = shist[b0], c1 = shist[b0 + 1], c2 = shist[b0 + 2], c3 = shist[b0 + 3];
        int cnt = c0 + c1 + c2 + c3;
        int s = cnt;
#pragma unroll
        for (int off = 1; off < 32; off <<= 1) {
            int o2 = __shfl_down_sync(0xFFFFFFFFu, s, off);
            if (lane + off < 32) s += o2;
        }
        if (lane == 0) swtot[wid] = s;
        __syncthreads();
        int above = 0;
#pragma unroll
        for (int w = 0; w < 32; w++)
            if (w > wid) above += swtot[w];
        int suffix = s + above;
        int cum = suffix - cnt;
        if (cum < krem && suffix >= krem) {
            int bin;
            if (cum + c3 >= krem)                bin = b0 + 3;
            else if (cum + c3 + c2 >= krem)      bin = b0 + 2;
            else if (cum + c3 + c2 + c1 >= krem) bin = b0 + 1;
            else                                 bin = b0;
            s_prefix = prefix | (unsigned)bin;
        }
        __syncthreads();
        prefix = s_prefix;
        __syncthreads();
    }

    // ---- final: sum of values strictly above threshold + tie fill ----
    float t = __uint_as_float(prefix);
    double s = 0.0;
    int c = 0;
#pragma unroll 4
    for (int i = tid; i < PP; i += TKT) {
        float x = v[i];
        if (x > t) { s += (double)x; c++; }
    }
    for (int off = 16; off > 0; off >>= 1) {
        s += __shfl_down_sync(0xFFFFFFFFu, s, off);
        c += __shfl_down_sync(0xFFFFFFFFu, c, off);
    }
    __shared__ double sd[32];
    __shared__ int sc[32];
    if (lane == 0) { sd[wid] = s; sc[wid] = c; }
    __syncthreads();
    if (tid == 0) {
        double S = 0.0;
        int C = 0;
        for (int w = 0; w < 32; w++) { S += sd[w]; C += sc[w]; }
        double res = S + (double)(k - C) * (double)t;
        atomicAdd(&g_topk, res);
    }
}

// ---------------- finalize (parallel) ----------------
__global__ void __launch_bounds__(64) k_final(float* out) {
    int t = threadIdx.x;            // 64 threads
    int lane = t & 31, wid = t >> 5;
    int np = g_numpos[t];
#pragma unroll
    for (int off = 16; off > 0; off >>= 1)
        np += __shfl_down_sync(0xFFFFFFFFu, np, off);
    __shared__ int snp[2];
    if (lane == 0) snp[wid] = np;
    __syncthreads();
    if (t == 0) {
        int tp = snp[0] + snp[1];
        double N = tp > 0 ? (double)tp : 1.0;
        out[0] = (float)(g_acc[0] / N);
        out[1] = (float)((g_acc[2] + g_topk) / N);
        out[2] = (float)(g_acc[1] / N);
    }
}

// ---------------- launch ----------------
extern "C" void kernel_launch(void* const* d_in, const int* in_sizes, int n_in,
                              void* d_out, int out_size) {
    const float *loc = nullptr, *conf = nullptr, *landm = nullptr;
    const float *priors = nullptr, *targets = nullptr;
    for (int i = 0; i < n_in; i++) {
        long long s = in_sizes[i];
        if (s == (long long)BB * PP * 4)       loc     = (const float*)d_in[i];
        else if (s == (long long)BB * PP * 3)  conf    = (const float*)d_in[i];
        else if (s == (long long)BB * PP * 10) landm   = (const float*)d_in[i];
        else if (s == (long long)PP * 4)       priors  = (const float*)d_in[i];
        else if (s == (long long)BB * GG * 15) targets = (const float*)d_in[i];
    }

    k_cell<<<128, 256>>>(priors);
    k_ssort<<<128, 256>>>(priors);
    k_match<<<dim3(PP / 1024, BB), 256>>>(targets);
    k_scatter<<<BB, 64>>>();
    k_losses<<<dim3(128, BB), 256>>>(conf, targets);
    k_tail<<<320, TKT>>>(loc, conf, landm, priors, targets);
    k_final<<<1, 64>>>((float*)d_out);
}

// round 13
// speedup vs baseline: 1.0785x; 1.0785x over previous
#include <cuda_runtime.h>

#define BB 64
#define PP 32768
#define GG 64

// ---------------- device scratch ----------------
__device__ int    g_cellv[PP];
__device__ int    g_chist[128 * 256];
__device__ float4 g_sppt[PP];     // sorted point-form priors
__device__ float  g_spar[PP];     // sorted areas
__device__ int    g_sidx[PP];     // sorted -> original index
__device__ int    g_btc[BB * PP]; // packed: (best_truth_idx<<1) | (ov>=0.35)
__device__ unsigned long long g_best[BB * GG];
__device__ float  g_lossc[BB * PP];
__device__ int    g_hist1[BB * 256];   // per-batch top-byte histogram
__device__ int    g_poslist[BB * PP];
__device__ int    g_segcnt[BB * 128];
__device__ int    g_numpos[BB];
__device__ int    g_anyvalid[BB];
__device__ double g_acc[3];
__device__ double g_topk;

__device__ __forceinline__ float sl1(float d) {
    float a = fabsf(d);
    return a < 1.0f ? 0.5f * d * d : a - 0.5f;
}

// ---------------- sort step 1 (+ fused global init) -------------------------
__global__ void __launch_bounds__(256) k_cell(const float* __restrict__ priors) {
    __shared__ int sh[256];
    int tid = threadIdx.x;
    int gt = blockIdx.x * 256 + tid;           // 0..32767
    // fused init
    if (gt < BB * GG) g_best[gt] = 0x00000000FFFFFFFFull;  // ratio=0, p=0
    if (gt < BB) g_numpos[gt] = 0;
    if (gt < 3) g_acc[gt] = 0.0;
    if (gt == 3) g_topk = 0.0;
    if (gt < BB * 256) g_hist1[gt] = 0;

    sh[tid] = 0;
    __syncthreads();
    float4 pr = ((const float4*)priors)[gt];
    int cx = min(7, max(0, (int)(pr.x * 8.0f)));
    int cy = min(7, max(0, (int)(pr.y * 8.0f)));
    float mwh = fmaxf(pr.z, pr.w);
    int sc = min(3, max(0, (int)((mwh - 0.02f) * 14.2857f)));
    int cell = ((cy * 8 + cx) << 2) | sc;
    g_cellv[gt] = cell;
    atomicAdd(&sh[cell], 1);
    __syncthreads();
    g_chist[blockIdx.x * 256 + tid] = sh[tid];
}

// ---------------- sort step 2: fused scan + rank-stable scatter -------------
__global__ void __launch_bounds__(256) k_ssort(const float* __restrict__ priors) {
    __shared__ int soff[256];
    __shared__ int sscan[256];
    __shared__ int scnt[8][256];
    int tid = threadIdx.x, lane = tid & 31, wid = tid >> 5;

    int mytot = 0, mypre = 0;
    int myck = blockIdx.x;
#pragma unroll 8
    for (int ch = 0; ch < 128; ch++) {
        int v = g_chist[ch * 256 + tid];
        mytot += v;
        if (ch < myck) mypre += v;
    }
    sscan[tid] = mytot;
    __syncthreads();
    for (int off = 1; off < 256; off <<= 1) {
        int v = (tid >= off) ? sscan[tid - off] : 0;
        __syncthreads();
        sscan[tid] += v;
        __syncthreads();
    }
    soff[tid] = sscan[tid] - mytot + mypre;
#pragma unroll
    for (int i = 0; i < 8; i++) scnt[i][tid] = 0;
    __syncthreads();

    int p = blockIdx.x * 256 + tid;
    int cell = g_cellv[p];
    atomicAdd(&scnt[wid][cell], 1);
    unsigned mk = __match_any_sync(0xFFFFFFFFu, cell);
    int rank = __popc(mk & ((1u << lane) - 1));
    __syncthreads();
    int before = 0;
    for (int w = 0; w < wid; w++) before += scnt[w][cell];
    int slot = soff[cell] + before + rank;

    float4 pr = ((const float4*)priors)[p];
    float4 pt = make_float4(pr.x - pr.z * 0.5f, pr.y - pr.w * 0.5f,
                            pr.x + pr.z * 0.5f, pr.y + pr.w * 0.5f);
    g_sppt[slot] = pt;
    g_spar[slot] = (pt.z - pt.x) * (pt.w - pt.y);
    g_sidx[slot] = p;
}

// ---------------- fused match: one culled pass ----------------
__global__ void __launch_bounds__(256) k_match(const float* __restrict__ targets) {
    __shared__ float sgx1[GG], sgy1[GG], sgx2[GG], sgy2[GG], sga[GG];
    __shared__ float s_r[8][GG];
    __shared__ int   s_ix[8][GG];

    int b = blockIdx.y, tid = threadIdx.x;
    int lane = tid & 31, wid = tid >> 5;

    if (tid < GG) {
        const float* t = targets + ((size_t)b * GG + tid) * 15;
        float x1 = t[0], y1 = t[1], x2 = t[2], y2 = t[3];
        sgx1[tid] = x1; sgy1[tid] = y1; sgx2[tid] = x2; sgy2[tid] = y2;
        sga[tid] = (x2 - x1) * (y2 - y1);
    }
    for (int i = tid; i < 8 * GG; i += 256) {
        ((float*)s_r)[i] = 0.0f;
        ((int*)s_ix)[i] = 0x7FFFFFFF;
    }
    __syncthreads();

    int s0 = blockIdx.x * 1024 + wid * 128 + lane;
    float4 q[4]; float qa[4]; int qi[4];
#pragma unroll
    for (int k = 0; k < 4; k++) {
        q[k] = g_sppt[s0 + 32 * k];
        qa[k] = g_spar[s0 + 32 * k];
        qi[k] = g_sidx[s0 + 32 * k];
    }
    // warp bbox over its 128 priors
    float bx1 = q[0].x, by1 = q[0].y, bx2 = q[0].z, by2 = q[0].w;
#pragma unroll
    for (int k = 1; k < 4; k++) {
        bx1 = fminf(bx1, q[k].x); by1 = fminf(by1, q[k].y);
        bx2 = fmaxf(bx2, q[k].z); by2 = fmaxf(by2, q[k].w);
    }
#pragma unroll
    for (int off = 16; off > 0; off >>= 1) {
        bx1 = fminf(bx1, __shfl_xor_sync(0xFFFFFFFFu, bx1, off));
        by1 = fminf(by1, __shfl_xor_sync(0xFFFFFFFFu, by1, off));
        bx2 = fmaxf(bx2, __shfl_xor_sync(0xFFFFFFFFu, bx2, off));
        by2 = fmaxf(by2, __shfl_xor_sync(0xFFFFFFFFu, by2, off));
    }

    // 64-bit GT hit mask
    bool h0 = sgx1[lane] < bx2 && sgx2[lane] > bx1 &&
              sgy1[lane] < by2 && sgy2[lane] > by1;
    bool h1 = sgx1[lane + 32] < bx2 && sgx2[lane + 32] > bx1 &&
              sgy1[lane + 32] < by2 && sgy2[lane + 32] > by1;
    unsigned m0 = __ballot_sync(0xFFFFFFFFu, h0);
    unsigned m1 = __ballot_sync(0xFFFFFFFFu, h1);
    unsigned long long mask =
        (unsigned long long)m0 | ((unsigned long long)m1 << 32);

    float bin[4], bun[4]; int bix[4];
#pragma unroll
    for (int k = 0; k < 4; k++) { bin[k] = 0.0f; bun[k] = 1.0f; bix[k] = 0; }

    while (mask) {
        int g = __ffsll((long long)mask) - 1;
        mask &= mask - 1;
        float x1 = sgx1[g], y1 = sgy1[g], x2 = sgx2[g], y2 = sgy2[g];
        float ar = sga[g];
        float ti[4], tu[4];
#pragma unroll
        for (int k = 0; k < 4; k++) {
            float lx = fmaxf(x1, q[k].x), ly = fmaxf(y1, q[k].y);
            float rx = fminf(x2, q[k].z), ry = fminf(y2, q[k].w);
            float w = fmaxf(rx - lx, 0.0f), h = fmaxf(ry - ly, 0.0f);
            float inter = w * h;
            float un = (ar + qa[k]) - inter;
            ti[k] = inter; tu[k] = un;
            if (inter * bun[k] > bin[k] * un) { bin[k] = inter; bun[k] = un; bix[k] = g; }
        }
        // local 4-way merge (cross-mult, keep-self on tie)
        float ri = ti[0], ru = tu[0]; int rp = qi[0];
#pragma unroll
        for (int k = 1; k < 4; k++)
            if (ti[k] * ru > ri * tu[k]) { ri = ti[k]; ru = tu[k]; rp = qi[k]; }
        // collapse to ratio; REDUX-based warp argmax
        float r = __fdividef(ri, ru);
        unsigned rb = __float_as_uint(r);          // r >= 0: bits monotone
        unsigned rmax = __reduce_max_sync(0xFFFFFFFFu, rb);
        if (rmax != 0u) {
            unsigned who = __ballot_sync(0xFFFFFFFFu, rb == rmax);
            int src = __ffs(who) - 1;
            int wp = __shfl_sync(0xFFFFFFFFu, rp, src);
            if (lane == 0) {
                s_r[wid][g] = __uint_as_float(rmax);
                s_ix[wid][g] = wp;
            }
        }
    }

    // per-prior results: packed (idx<<1)|thresh, 4B scatter stores
#pragma unroll
    for (int k = 0; k < 4; k++) {
        int flag = (bin[k] >= 0.35f * bun[k]) ? 1 : 0;
        g_btc[(size_t)b * PP + qi[k]] = (bix[k] << 1) | flag;
    }

    __syncthreads();
    // block merge per g + global atomic merge
    if (tid < GG) {
        float r = s_r[0][tid]; int rp = s_ix[0][tid];
#pragma unroll
        for (int w = 1; w < 8; w++) {
            float orr = s_r[w][tid]; int op = s_ix[w][tid];
            if (orr > r || (orr == r && op < rp)) { r = orr; rp = op; }
        }
        if (rp != 0x7FFFFFFF) {
            unsigned long long key =
                ((unsigned long long)__float_as_uint(r) << 32) |
                (unsigned)(~(unsigned)rp);
            atomicMax(&g_best[b * GG + tid], key);
        }
    }
}

// ---------------- parallel scatter corrections (packed) --------------------
__global__ void __launch_bounds__(64) k_scatter() {
    int b = blockIdx.x;
    int g = threadIdx.x;
    __shared__ int sp[GG];
    __shared__ int sv[GG];
    __shared__ int sany;
    if (g == 0) sany = 0;

    unsigned long long key = g_best[b * GG + g];
    int p = (int)(~(unsigned)(key & 0xFFFFFFFFull));
    float ratio = __uint_as_float((unsigned)(key >> 32));
    int valid = ratio >= 0.2f ? 1 : 0;
    sp[g] = p;
    sv[g] = valid;
    __syncthreads();

    if (valid) sany = 1;

    bool lastwins = true;
    int anyv = 0;
    for (int g2 = 0; g2 < GG; g2++) {
        if (sp[g2] == p) {
            if (sv[g2]) anyv = 1;
            if (g2 > g) lastwins = false;
        }
    }
    if (lastwins) {
        size_t o = (size_t)b * PP + p;
        int old = g_btc[o];
        g_btc[o] = (g << 1) | ((old & 1) | anyv);
    }

    __syncthreads();
    if (g == 0) g_anyvalid[b] = sany;
}

// ---------------- slim per-prior loss_c + pos compaction + hist pass 1 -----
__global__ void __launch_bounds__(256) k_losses(const float* __restrict__ conf_data,
                                                const float* __restrict__ targets) {
    __shared__ int swc[8];
    __shared__ int shist[256];
    int b = blockIdx.y, tid = threadIdx.x;
    int lane = tid & 31, wid = tid >> 5;
    shist[tid] = 0;

    int p = blockIdx.x * 256 + tid;
    size_t o = (size_t)b * PP + p;
    int packed = g_btc[o];
    int g = packed >> 1;
    int av = g_anyvalid[b];

    int conf = 0;
    if (av && (packed & 1))
        conf = (int)__ldg(&targets[((size_t)b * GG + g) * 15 + 14]);

    const float* cd = conf_data + o * 3;
    float c0 = cd[0], c1 = cd[1], c2 = cd[2];
    float mx = fmaxf(c0, fmaxf(c1, c2));
    float lse = mx + __logf(__expf(c0 - mx) + __expf(c1 - mx) + __expf(c2 - mx));
    float gathered = (conf == 0) ? c0 : ((conf == 1) ? c1 : c2);
    float lcv = lse - gathered;
    bool pos = conf > 0;
    float stored = pos ? 0.0f : lcv;
    g_lossc[o] = stored;

    unsigned m = __ballot_sync(0xFFFFFFFFu, pos);
    if (lane == 0) swc[wid] = __popc(m);
    __syncthreads();

    atomicAdd(&shist[__float_as_uint(stored) >> 24], 1);

    int base = 0;
#pragma unroll
    for (int w = 0; w < 8; w++)
        if (w < wid) base += swc[w];
    if (pos)
        g_poslist[((size_t)b * 128 + blockIdx.x) * 256 + base +
                  __popc(m & ((1u << lane) - 1))] = p;
    __syncthreads();

    if (shist[tid]) atomicAdd(&g_hist1[b * 256 + tid], shist[tid]);
    if (tid == 0) {
        int c = 0;
#pragma unroll
        for (int w = 0; w < 8; w++) c += swc[w];
        g_segcnt[b * 128 + blockIdx.x] = c;
        if (c) atomicAdd(&g_numpos[b], c);
    }
}

// ---------------- fused tail: blocks 0-63 topk, blocks 64-319 pos ----------
#define TKT 1024
__global__ void __launch_bounds__(TKT) k_tail(const float* __restrict__ loc_data,
                                              const float* __restrict__ conf_data,
                                              const float* __restrict__ landm_data,
                                              const float* __restrict__ priors,
                                              const float* __restrict__ targets) {
    int tid = threadIdx.x, lane = tid & 31, wid = tid >> 5;

    if (blockIdx.x >= 64) {
        // ---- pos path: one segment per warp ----
        int seg = (blockIdx.x - 64) * 32 + wid;
        int cnt = g_segcnt[seg];
        int b = seg >> 7;
        size_t segbase = (size_t)seg * 256;
        double dl = 0.0, dlm = 0.0, dcp = 0.0;
        for (int i = lane; i < cnt; i += 32) {
            int p = g_poslist[segbase + i];
            size_t o = (size_t)b * PP + p;
            int g = g_btc[o] >> 1;
            const float* t = targets + ((size_t)b * GG + g) * 15;
            int conf = (int)t[14];

            const float* cd = conf_data + o * 3;
            float c0 = cd[0], c1 = cd[1], c2 = cd[2];
            float mx = fmaxf(c0, fmaxf(c1, c2));
            float lse = mx + __logf(__expf(c0 - mx) + __expf(c1 - mx) + __expf(c2 - mx));
            dcp += (double)(lse - ((conf == 1) ? c1 : c2));

            float4 pr = ((const float4*)priors)[p];
            float dwx = 0.1f * pr.z, dwy = 0.1f * pr.w;
            float m0 = t[0], m1 = t[1], m2 = t[2], m3 = t[3];
            float gcx = ((m0 + m2) * 0.5f - pr.x) / dwx;
            float gcy = ((m1 + m3) * 0.5f - pr.y) / dwy;
            float gw2 = __logf((m2 - m0) / pr.z) * 5.0f;
            float gh2 = __logf((m3 - m1) / pr.w) * 5.0f;
            const float* ld = loc_data + o * 4;
            dl += (double)(sl1(ld[0] - gcx) + sl1(ld[1] - gcy) +
                           sl1(ld[2] - gw2) + sl1(ld[3] - gh2));

            const float* lt = t + 4;
            const float* lm = landm_data + o * 10;
            int nd = (conf == 1) ? 10 : 4;
            float s = 0.0f;
            for (int j = 0; j < nd; j += 2) {
                float lx = (lt[j] - pr.x) / dwx;
                float ly = (lt[j + 1] - pr.y) / dwy;
                s += sl1(lm[j] - lx) + sl1(lm[j + 1] - ly);
            }
            dlm += (double)s;
        }
#pragma unroll
        for (int off = 16; off > 0; off >>= 1) {
            dl  += __shfl_down_sync(0xFFFFFFFFu, dl, off);
            dlm += __shfl_down_sync(0xFFFFFFFFu, dlm, off);
            dcp += __shfl_down_sync(0xFFFFFFFFu, dcp, off);
        }
        __shared__ double sdp[3][32];
        if (lane == 0) { sdp[0][wid] = dl; sdp[1][wid] = dlm; sdp[2][wid] = dcp; }
        __syncthreads();
        if (tid == 0) {
            double a = 0, b2 = 0, c = 0;
#pragma unroll
            for (int w = 0; w < 32; w++) { a += sdp[0][w]; b2 += sdp[1][w]; c += sdp[2][w]; }
            if (a != 0.0 || b2 != 0.0 || c != 0.0) {
                atomicAdd(&g_acc[0], a);
                atomicAdd(&g_acc[1], b2);
                atomicAdd(&g_acc[2], c);
            }
        }
        return;
    }

    // ---- topk path ----
    int b = blockIdx.x;
    int np = g_numpos[b];
    long long kk = 7LL * np;
    if (kk > PP - 1) kk = PP - 1;
    if (kk <= 0) return;
    int k = (int)kk;

    const float* v = g_lossc + (size_t)b * PP;

    __shared__ int shist[4096];
    __shared__ int swtot[32];
    __shared__ unsigned s_prefix;
    __shared__ int s_krem;

    int krem = k;
    unsigned prefix;

    // ---- pass 1: top byte from precomputed g_hist1 ----
    {
        int cnt = (tid < 256) ? g_hist1[b * 256 + tid] : 0;
        int s = cnt;
#pragma unroll
        for (int off = 1; off < 32; off <<= 1) {
            int o2 = __shfl_down_sync(0xFFFFFFFFu, s, off);
            if (lane + off < 32) s += o2;
        }
        if (lane == 0) swtot[wid] = s;
        __syncthreads();
        if (tid < 256) {
            int above = 0;
#pragma unroll
            for (int w = 0; w < 8; w++)
                if (w > wid) above += swtot[w];
            int suffix = s + above;
            if (suffix >= krem && suffix - cnt < krem) {
                s_prefix = (unsigned)tid << 24;
                s_krem = krem - (suffix - cnt);
            }
        }
        __syncthreads();
        prefix = s_prefix;
        krem = s_krem;
        __syncthreads();
    }

    // ---- pass 2: bits 23..12 ----
    for (int i = tid; i < 4096; i += TKT) shist[i] = 0;
    __syncthreads();
#pragma unroll 4
    for (int i = tid; i < PP; i += TKT) {
        unsigned u = __float_as_uint(v[i]);
        if ((u & 0xFF000000u) == prefix)
            atomicAdd(&shist[(u >> 12) & 0xFFFu], 1);
    }
    __syncthreads();
    {
        int b0 = tid * 4;
        int c0 = shist[b0], c1 = shist[b0 + 1], c2 = shist[b0 + 2], c3 = shist[b0 + 3];
        int cnt = c0 + c1 + c2 + c3;
        int s = cnt;
#pragma unroll
        for (int off = 1; off < 32; off <<= 1) {
            int o2 = __shfl_down_sync(0xFFFFFFFFu, s, off);
            if (lane + off < 32) s += o2;
        }
        if (lane == 0) swtot[wid] = s;
        __syncthreads();
        int above = 0;
#pragma unroll
        for (int w = 0; w < 32; w++)
            if (w > wid) above += swtot[w];
        int suffix = s + above;
        int cum = suffix - cnt;
        if (cum < krem && suffix >= krem) {
            int bin, c;
            if (cum + c3 >= krem)                { bin = b0 + 3; c = cum; }
            else if (cum + c3 + c2 >= krem)      { bin = b0 + 2; c = cum + c3; }
            else if (cum + c3 + c2 + c1 >= krem) { bin = b0 + 1; c = cum + c3 + c2; }
            else                                 { bin = b0;     c = cum + c3 + c2 + c1; }
            s_prefix = prefix | ((unsigned)bin << 12);
            s_krem = krem - c;
        }
        __syncthreads();
        prefix = s_prefix;
        krem = s_krem;
        __syncthreads();
    }

    // ---- pass 3: bits 11..0 ----
    for (int i = tid; i < 4096; i += TKT) shist[i] = 0;
    __syncthreads();
#pragma unroll 4
    for (int i = tid; i < PP; i += TKT) {
        unsigned u = __float_as_uint(v[i]);
        if ((u & 0xFFFFF000u) == prefix)
            atomicAdd(&shist[u & 0xFFFu], 1);
    }
    __syncthreads();
    {
        int b0 = tid * 4;
        int c0 = shist[b0], c1 = shist[b0 + 1], c2 = shist[b0 + 2], c3 = shist[b0 + 3];
        int cnt = c0 + c1 + c2 + c3;
        int s = cnt;
#pragma unroll
        for (int off = 1; off < 32; off <<= 1) {
            int o2 = __shfl_down_sync(0xFFFFFFFFu, s, off);
            if (lane + off < 32) s += o2;
        }
        if (lane == 0) swtot[wid] = s;
        __syncthreads();
        int above = 0;
#pragma unroll
        for (int w = 0; w < 32; w++)
            if (w > wid) above += swtot[w];
        int suffix = s + above;
        int cum = suffix - cnt;
        if (cum < krem && suffix >= krem) {
            int bin;
            if (cum + c3 >= krem)                bin = b0 + 3;
            else if (cum + c3 + c2 >= krem)      bin = b0 + 2;
            else if (cum + c3 + c2 + c1 >= krem) bin = b0 + 1;
            else                                 bin = b0;
            s_prefix = prefix | (unsigned)bin;
        }
        __syncthreads();
        prefix = s_prefix;
        __syncthreads();
    }

    // ---- final: sum of values strictly above threshold + tie fill ----
    float t = __uint_as_float(prefix);
    double s = 0.0;
    int c = 0;
#pragma unroll 4
    for (int i = tid; i < PP; i += TKT) {
        float x = v[i];
        if (x > t) { s += (double)x; c++; }
    }
    for (int off = 16; off > 0; off >>= 1) {
        s += __shfl_down_sync(0xFFFFFFFFu, s, off);
        c += __shfl_down_sync(0xFFFFFFFFu, c, off);
    }
    __shared__ double sd[32];
    __shared__ int sc[32];
    if (lane == 0) { sd[wid] = s; sc[wid] = c; }
    __syncthreads();
    if (tid == 0) {
        double S = 0.0;
        int C = 0;
        for (int w = 0; w < 32; w++) { S += sd[w]; C += sc[w]; }
        double res = S + (double)(k - C) * (double)t;
        atomicAdd(&g_topk, res);
    }
}

// ---------------- finalize (parallel) ----------------
__global__ void __launch_bounds__(64) k_final(float* out) {
    int t = threadIdx.x;
    int lane = t & 31, wid = t >> 5;
    int np = g_numpos[t];
#pragma unroll
    for (int off = 16; off > 0; off >>= 1)
        np += __shfl_down_sync(0xFFFFFFFFu, np, off);
    __shared__ int snp[2];
    if (lane == 0) snp[wid] = np;
    __syncthreads();
    if (t == 0) {
        int tp = snp[0] + snp[1];
        double N = tp > 0 ? (double)tp : 1.0;
        out[0] = (float)(g_acc[0] / N);
        out[1] = (float)((g_acc[2] + g_topk) / N);
        out[2] = (float)(g_acc[1] / N);
    }
}

// ---------------- launch ----------------
extern "C" void kernel_launch(void* const* d_in, const int* in_sizes, int n_in,
                              void* d_out, int out_size) {
    const float *loc = nullptr, *conf = nullptr, *landm = nullptr;
    const float *priors = nullptr, *targets = nullptr;
    for (int i = 0; i < n_in; i++) {
        long long s = in_sizes[i];
        if (s == (long long)BB * PP * 4)       loc     = (const float*)d_in[i];
        else if (s == (long long)BB * PP * 3)  conf    = (const float*)d_in[i];
        else if (s == (long long)BB * PP * 10) landm   = (const float*)d_in[i];
        else if (s == (long long)PP * 4)       priors  = (const float*)d_in[i];
        else if (s == (long long)BB * GG * 15) targets = (const float*)d_in[i];
    }

    k_cell<<<128, 256>>>(priors);
    k_ssort<<<128, 256>>>(priors);
    k_match<<<dim3(PP / 1024, BB), 256>>>(targets);
    k_scatter<<<BB, 64>>>();
    k_losses<<<dim3(128, BB), 256>>>(conf, targets);
    k_tail<<<320, TKT>>>(loc, conf, landm, priors, targets);
    k_final<<<1, 64>>>((float*)d_out);
}

// round 14
// speedup vs baseline: 1.1003x; 1.0202x over previous
#include <cuda_runtime.h>

#define BB 64
#define PP 32768
#define GG 64

// ---------------- device scratch ----------------
__device__ int    g_cellv[PP];
__device__ int    g_chist[128 * 256];
__device__ float4 g_sppt[PP];     // sorted point-form priors
__device__ float  g_spar[PP];     // sorted areas
__device__ int    g_sidx[PP];     // sorted -> original index
__device__ int    g_btc[BB * PP]; // packed: (best_truth_idx<<1) | (ov>=0.35)
__device__ unsigned long long g_best[BB * GG];
__device__ float  g_lossc[BB * PP];
__device__ int    g_hist1[BB * 256];   // per-batch top-byte histogram
__device__ int    g_poslist[BB * PP];
__device__ int    g_segcnt[BB * 128];
__device__ int    g_numpos[BB];
__device__ int    g_tp;
__device__ int    g_done;
__device__ double g_acc[3];
__device__ double g_topk;

__device__ __forceinline__ float sl1(float d) {
    float a = fabsf(d);
    return a < 1.0f ? 0.5f * d * d : a - 0.5f;
}

// ---------------- sort step 1 (+ fused global init) -------------------------
__global__ void __launch_bounds__(256) k_cell(const float* __restrict__ priors) {
    __shared__ int sh[256];
    int tid = threadIdx.x;
    int gt = blockIdx.x * 256 + tid;           // 0..32767
    // fused init
    if (gt < BB * GG) g_best[gt] = 0x00000000FFFFFFFFull;  // ratio=0, p=0
    if (gt < BB) g_numpos[gt] = 0;
    if (gt < 3) g_acc[gt] = 0.0;
    if (gt == 3) g_topk = 0.0;
    if (gt == 4) g_tp = 0;
    if (gt == 5) g_done = 0;
    if (gt < BB * 256) g_hist1[gt] = 0;

    sh[tid] = 0;
    __syncthreads();
    float4 pr = ((const float4*)priors)[gt];
    int cx = min(7, max(0, (int)(pr.x * 8.0f)));
    int cy = min(7, max(0, (int)(pr.y * 8.0f)));
    float mwh = fmaxf(pr.z, pr.w);
    int sc = min(3, max(0, (int)((mwh - 0.02f) * 14.2857f)));
    int cell = ((cy * 8 + cx) << 2) | sc;
    g_cellv[gt] = cell;
    atomicAdd(&sh[cell], 1);
    __syncthreads();
    g_chist[blockIdx.x * 256 + tid] = sh[tid];
}

// ---------------- sort step 2: fused scan + rank-stable scatter -------------
__global__ void __launch_bounds__(256) k_ssort(const float* __restrict__ priors) {
    __shared__ int soff[256];
    __shared__ int sscan[256];
    __shared__ int scnt[8][256];
    int tid = threadIdx.x, lane = tid & 31, wid = tid >> 5;

    int mytot = 0, mypre = 0;
    int myck = blockIdx.x;
#pragma unroll 8
    for (int ch = 0; ch < 128; ch++) {
        int v = g_chist[ch * 256 + tid];
        mytot += v;
        if (ch < myck) mypre += v;
    }
    sscan[tid] = mytot;
    __syncthreads();
    for (int off = 1; off < 256; off <<= 1) {
        int v = (tid >= off) ? sscan[tid - off] : 0;
        __syncthreads();
        sscan[tid] += v;
        __syncthreads();
    }
    soff[tid] = sscan[tid] - mytot + mypre;
#pragma unroll
    for (int i = 0; i < 8; i++) scnt[i][tid] = 0;
    __syncthreads();

    int p = blockIdx.x * 256 + tid;
    int cell = g_cellv[p];
    atomicAdd(&scnt[wid][cell], 1);
    unsigned mk = __match_any_sync(0xFFFFFFFFu, cell);
    int rank = __popc(mk & ((1u << lane) - 1));
    __syncthreads();
    int before = 0;
    for (int w = 0; w < wid; w++) before += scnt[w][cell];
    int slot = soff[cell] + before + rank;

    float4 pr = ((const float4*)priors)[p];
    float4 pt = make_float4(pr.x - pr.z * 0.5f, pr.y - pr.w * 0.5f,
                            pr.x + pr.z * 0.5f, pr.y + pr.w * 0.5f);
    g_sppt[slot] = pt;
    g_spar[slot] = (pt.z - pt.x) * (pt.w - pt.y);
    g_sidx[slot] = p;
}

// ---------------- fused match: one culled pass ----------------
__global__ void __launch_bounds__(256) k_match(const float* __restrict__ targets) {
    __shared__ float sgx1[GG], sgy1[GG], sgx2[GG], sgy2[GG], sga[GG];
    __shared__ float s_r[8][GG];
    __shared__ int   s_ix[8][GG];

    int b = blockIdx.y, tid = threadIdx.x;
    int lane = tid & 31, wid = tid >> 5;

    if (tid < GG) {
        const float* t = targets + ((size_t)b * GG + tid) * 15;
        float x1 = t[0], y1 = t[1], x2 = t[2], y2 = t[3];
        sgx1[tid] = x1; sgy1[tid] = y1; sgx2[tid] = x2; sgy2[tid] = y2;
        sga[tid] = (x2 - x1) * (y2 - y1);
    }
    for (int i = tid; i < 8 * GG; i += 256) {
        ((float*)s_r)[i] = 0.0f;
        ((int*)s_ix)[i] = 0x7FFFFFFF;
    }
    __syncthreads();

    int s0 = blockIdx.x * 1024 + wid * 128 + lane;
    float4 q[4]; float qa[4]; int qi[4];
#pragma unroll
    for (int k = 0; k < 4; k++) {
        q[k] = g_sppt[s0 + 32 * k];
        qa[k] = g_spar[s0 + 32 * k];
        qi[k] = g_sidx[s0 + 32 * k];
    }
    // warp bbox over its 128 priors
    float bx1 = q[0].x, by1 = q[0].y, bx2 = q[0].z, by2 = q[0].w;
#pragma unroll
    for (int k = 1; k < 4; k++) {
        bx1 = fminf(bx1, q[k].x); by1 = fminf(by1, q[k].y);
        bx2 = fmaxf(bx2, q[k].z); by2 = fmaxf(by2, q[k].w);
    }
#pragma unroll
    for (int off = 16; off > 0; off >>= 1) {
        bx1 = fminf(bx1, __shfl_xor_sync(0xFFFFFFFFu, bx1, off));
        by1 = fminf(by1, __shfl_xor_sync(0xFFFFFFFFu, by1, off));
        bx2 = fmaxf(bx2, __shfl_xor_sync(0xFFFFFFFFu, bx2, off));
        by2 = fmaxf(by2, __shfl_xor_sync(0xFFFFFFFFu, by2, off));
    }

    // 64-bit GT hit mask
    bool h0 = sgx1[lane] < bx2 && sgx2[lane] > bx1 &&
              sgy1[lane] < by2 && sgy2[lane] > by1;
    bool h1 = sgx1[lane + 32] < bx2 && sgx2[lane + 32] > bx1 &&
              sgy1[lane + 32] < by2 && sgy2[lane + 32] > by1;
    unsigned m0 = __ballot_sync(0xFFFFFFFFu, h0);
    unsigned m1 = __ballot_sync(0xFFFFFFFFu, h1);
    unsigned long long mask =
        (unsigned long long)m0 | ((unsigned long long)m1 << 32);

    float bin[4], bun[4]; int bix[4];
#pragma unroll
    for (int k = 0; k < 4; k++) { bin[k] = 0.0f; bun[k] = 1.0f; bix[k] = 0; }

    while (mask) {
        int g = __ffsll((long long)mask) - 1;
        mask &= mask - 1;
        float x1 = sgx1[g], y1 = sgy1[g], x2 = sgx2[g], y2 = sgy2[g];
        float ar = sga[g];
        float ti[4], tu[4];
#pragma unroll
        for (int k = 0; k < 4; k++) {
            float lx = fmaxf(x1, q[k].x), ly = fmaxf(y1, q[k].y);
            float rx = fminf(x2, q[k].z), ry = fminf(y2, q[k].w);
            float w = fmaxf(rx - lx, 0.0f), h = fmaxf(ry - ly, 0.0f);
            float inter = w * h;
            float un = (ar + qa[k]) - inter;
            ti[k] = inter; tu[k] = un;
            if (inter * bun[k] > bin[k] * un) { bin[k] = inter; bun[k] = un; bix[k] = g; }
        }
        // local 4-way merge (cross-mult, keep-self on tie)
        float ri = ti[0], ru = tu[0]; int rp = qi[0];
#pragma unroll
        for (int k = 1; k < 4; k++)
            if (ti[k] * ru > ri * tu[k]) { ri = ti[k]; ru = tu[k]; rp = qi[k]; }
        // collapse to ratio; REDUX-based warp argmax
        float r = __fdividef(ri, ru);
        unsigned rb = __float_as_uint(r);          // r >= 0: bits monotone
        unsigned rmax = __reduce_max_sync(0xFFFFFFFFu, rb);
        if (rmax != 0u) {
            unsigned who = __ballot_sync(0xFFFFFFFFu, rb == rmax);
            int src = __ffs(who) - 1;
            int wp = __shfl_sync(0xFFFFFFFFu, rp, src);
            if (lane == 0) {
                s_r[wid][g] = __uint_as_float(rmax);
                s_ix[wid][g] = wp;
            }
        }
    }

    // per-prior results: packed (idx<<1)|thresh, 4B scatter stores
#pragma unroll
    for (int k = 0; k < 4; k++) {
        int flag = (bin[k] >= 0.35f * bun[k]) ? 1 : 0;
        g_btc[(size_t)b * PP + qi[k]] = (bix[k] << 1) | flag;
    }

    __syncthreads();
    // block merge per g + global atomic merge
    if (tid < GG) {
        float r = s_r[0][tid]; int rp = s_ix[0][tid];
#pragma unroll
        for (int w = 1; w < 8; w++) {
            float orr = s_r[w][tid]; int op = s_ix[w][tid];
            if (orr > r || (orr == r && op < rp)) { r = orr; rp = op; }
        }
        if (rp != 0x7FFFFFFF) {
            unsigned long long key =
                ((unsigned long long)__float_as_uint(r) << 32) |
                (unsigned)(~(unsigned)rp);
            atomicMax(&g_best[b * GG + tid], key);
        }
    }
}

// ---------------- loss_c + inline scatter + pos compaction + hist ----------
__global__ void __launch_bounds__(256) k_losses(const float* __restrict__ conf_data,
                                                const float* __restrict__ targets) {
    __shared__ int swc[8];
    __shared__ int shist[256];
    __shared__ int s_og[256];   // override g per in-window prior (atomicMax)
    __shared__ int s_ov[256];   // override valid OR
    __shared__ int s_av;
    int b = blockIdx.y, tid = threadIdx.x;
    int lane = tid & 31, wid = tid >> 5;
    shist[tid] = 0;
    s_og[tid] = -1;
    s_ov[tid] = 0;
    if (tid == 0) s_av = 0;
    __syncthreads();

    int pbase = blockIdx.x * 256;
    if (tid < GG) {
        unsigned long long key = g_best[b * GG + tid];
        int pg = (int)(~(unsigned)(key & 0xFFFFFFFFull));
        float ratio = __uint_as_float((unsigned)(key >> 32));
        int valid = ratio >= 0.2f ? 1 : 0;
        if (valid) s_av = 1;                     // benign race, same value
        int loc = pg - pbase;
        if (loc >= 0 && loc < 256) {
            atomicMax(&s_og[loc], tid);          // last-wins: highest g
            if (valid) atomicOr(&s_ov[loc], 1);
        }
    }
    __syncthreads();

    int p = pbase + tid;
    size_t o = (size_t)b * PP + p;
    int packed = g_btc[o];
    int g = packed >> 1;
    int flag = packed & 1;
    if (s_og[tid] >= 0) {
        g = s_og[tid];
        flag |= s_ov[tid];
        g_btc[o] = (g << 1) | flag;              // write-back for tail pos path
    }

    int conf = 0;
    if (s_av && flag)
        conf = (int)__ldg(&targets[((size_t)b * GG + g) * 15 + 14]);

    const float* cd = conf_data + o * 3;
    float c0 = cd[0], c1 = cd[1], c2 = cd[2];
    float mx = fmaxf(c0, fmaxf(c1, c2));
    float lse = mx + __logf(__expf(c0 - mx) + __expf(c1 - mx) + __expf(c2 - mx));
    float gathered = (conf == 0) ? c0 : ((conf == 1) ? c1 : c2);
    float lcv = lse - gathered;
    bool pos = conf > 0;
    float stored = pos ? 0.0f : lcv;
    g_lossc[o] = stored;

    unsigned m = __ballot_sync(0xFFFFFFFFu, pos);
    if (lane == 0) swc[wid] = __popc(m);
    __syncthreads();

    atomicAdd(&shist[__float_as_uint(stored) >> 24], 1);

    int base = 0;
#pragma unroll
    for (int w = 0; w < 8; w++)
        if (w < wid) base += swc[w];
    if (pos)
        g_poslist[((size_t)b * 128 + blockIdx.x) * 256 + base +
                  __popc(m & ((1u << lane) - 1))] = p;
    __syncthreads();

    if (shist[tid]) atomicAdd(&g_hist1[b * 256 + tid], shist[tid]);
    if (tid == 0) {
        int c = 0;
#pragma unroll
        for (int w = 0; w < 8; w++) c += swc[w];
        g_segcnt[b * 128 + blockIdx.x] = c;
        if (c) {
            atomicAdd(&g_numpos[b], c);
            atomicAdd(&g_tp, c);
        }
    }
}

// ---------------- fused tail: topk (0-63) + pos (64-319) + final ------------
#define TKT 1024
__global__ void __launch_bounds__(TKT) k_tail(const float* __restrict__ loc_data,
                                              const float* __restrict__ conf_data,
                                              const float* __restrict__ landm_data,
                                              const float* __restrict__ priors,
                                              const float* __restrict__ targets,
                                              float* __restrict__ out) {
    int tid = threadIdx.x, lane = tid & 31, wid = tid >> 5;

    if (blockIdx.x >= 64) {
        // ---- pos path: one segment per warp ----
        int seg = (blockIdx.x - 64) * 32 + wid;
        int cnt = g_segcnt[seg];
        int b = seg >> 7;
        size_t segbase = (size_t)seg * 256;
        double dl = 0.0, dlm = 0.0, dcp = 0.0;
        for (int i = lane; i < cnt; i += 32) {
            int p = g_poslist[segbase + i];
            size_t o = (size_t)b * PP + p;
            int g = g_btc[o] >> 1;
            const float* t = targets + ((size_t)b * GG + g) * 15;
            int conf = (int)t[14];

            const float* cd = conf_data + o * 3;
            float c0 = cd[0], c1 = cd[1], c2 = cd[2];
            float mx = fmaxf(c0, fmaxf(c1, c2));
            float lse = mx + __logf(__expf(c0 - mx) + __expf(c1 - mx) + __expf(c2 - mx));
            dcp += (double)(lse - ((conf == 1) ? c1 : c2));

            float4 pr = ((const float4*)priors)[p];
            float dwx = 0.1f * pr.z, dwy = 0.1f * pr.w;
            float m0 = t[0], m1 = t[1], m2 = t[2], m3 = t[3];
            float gcx = ((m0 + m2) * 0.5f - pr.x) / dwx;
            float gcy = ((m1 + m3) * 0.5f - pr.y) / dwy;
            float gw2 = __logf((m2 - m0) / pr.z) * 5.0f;
            float gh2 = __logf((m3 - m1) / pr.w) * 5.0f;
            const float* ld = loc_data + o * 4;
            dl += (double)(sl1(ld[0] - gcx) + sl1(ld[1] - gcy) +
                           sl1(ld[2] - gw2) + sl1(ld[3] - gh2));

            const float* lt = t + 4;
            const float* lm = landm_data + o * 10;
            int nd = (conf == 1) ? 10 : 4;
            float s = 0.0f;
            for (int j = 0; j < nd; j += 2) {
                float lx = (lt[j] - pr.x) / dwx;
                float ly = (lt[j + 1] - pr.y) / dwy;
                s += sl1(lm[j] - lx) + sl1(lm[j + 1] - ly);
            }
            dlm += (double)s;
        }
#pragma unroll
        for (int off = 16; off > 0; off >>= 1) {
            dl  += __shfl_down_sync(0xFFFFFFFFu, dl, off);
            dlm += __shfl_down_sync(0xFFFFFFFFu, dlm, off);
            dcp += __shfl_down_sync(0xFFFFFFFFu, dcp, off);
        }
        __shared__ double sdp[3][32];
        if (lane == 0) { sdp[0][wid] = dl; sdp[1][wid] = dlm; sdp[2][wid] = dcp; }
        __syncthreads();
        if (tid == 0) {
            double a = 0, b2 = 0, c = 0;
#pragma unroll
            for (int w = 0; w < 32; w++) { a += sdp[0][w]; b2 += sdp[1][w]; c += sdp[2][w]; }
            if (a != 0.0 || b2 != 0.0 || c != 0.0) {
                atomicAdd(&g_acc[0], a);
                atomicAdd(&g_acc[1], b2);
                atomicAdd(&g_acc[2], c);
            }
        }
    } else {
        // ---- topk path ----
        int b = blockIdx.x;
        int np = g_numpos[b];
        long long kk = 7LL * np;
        if (kk > PP - 1) kk = PP - 1;
        if (kk > 0) {
            int k = (int)kk;
            const float* v = g_lossc + (size_t)b * PP;

            __shared__ int shist[4096];
            __shared__ int swtot[32];
            __shared__ unsigned s_prefix;
            __shared__ int s_krem;

            int krem = k;
            unsigned prefix;

            // pass 1: top byte from precomputed g_hist1
            {
                int cnt = (tid < 256) ? g_hist1[b * 256 + tid] : 0;
                int s = cnt;
#pragma unroll
                for (int off = 1; off < 32; off <<= 1) {
                    int o2 = __shfl_down_sync(0xFFFFFFFFu, s, off);
                    if (lane + off < 32) s += o2;
                }
                if (lane == 0) swtot[wid] = s;
                __syncthreads();
                if (tid < 256) {
                    int above = 0;
#pragma unroll
                    for (int w = 0; w < 8; w++)
                        if (w > wid) above += swtot[w];
                    int suffix = s + above;
                    if (suffix >= krem && suffix - cnt < krem) {
                        s_prefix = (unsigned)tid << 24;
                        s_krem = krem - (suffix - cnt);
                    }
                }
                __syncthreads();
                prefix = s_prefix;
                krem = s_krem;
                __syncthreads();
            }

            // pass 2: bits 23..12
            for (int i = tid; i < 4096; i += TKT) shist[i] = 0;
            __syncthreads();
#pragma unroll 4
            for (int i = tid; i < PP; i += TKT) {
                unsigned u = __float_as_uint(v[i]);
                if ((u & 0xFF000000u) == prefix)
                    atomicAdd(&shist[(u >> 12) & 0xFFFu], 1);
            }
            __syncthreads();
            {
                int b0 = tid * 4;
                int c0 = shist[b0], c1 = shist[b0 + 1], c2 = shist[b0 + 2], c3 = shist[b0 + 3];
                int cnt = c0 + c1 + c2 + c3;
                int s = cnt;
#pragma unroll
                for (int off = 1; off < 32; off <<= 1) {
                    int o2 = __shfl_down_sync(0xFFFFFFFFu, s, off);
                    if (lane + off < 32) s += o2;
                }
                if (lane == 0) swtot[wid] = s;
                __syncthreads();
                int above = 0;
#pragma unroll
                for (int w = 0; w < 32; w++)
                    if (w > wid) above += swtot[w];
                int suffix = s + above;
                int cum = suffix - cnt;
                if (cum < krem && suffix >= krem) {
                    int bin, c;
                    if (cum + c3 >= krem)                { bin = b0 + 3; c = cum; }
                    else if (cum + c3 + c2 >= krem)      { bin = b0 + 2; c = cum + c3; }
                    else if (cum + c3 + c2 + c1 >= krem) { bin = b0 + 1; c = cum + c3 + c2; }
                    else                                 { bin = b0;     c = cum + c3 + c2 + c1; }
                    s_prefix = prefix | ((unsigned)bin << 12);
                    s_krem = krem - c;
                }
                __syncthreads();
                prefix = s_prefix;
                krem = s_krem;
                __syncthreads();
            }

            // pass 3: bits 11..0
            for (int i = tid; i < 4096; i += TKT) shist[i] = 0;
            __syncthreads();
#pragma unroll 4
            for (int i = tid; i < PP; i += TKT) {
                unsigned u = __float_as_uint(v[i]);
                if ((u & 0xFFFFF000u) == prefix)
                    atomicAdd(&shist[u & 0xFFFu], 1);
            }
            __syncthreads();
            {
                int b0 = tid * 4;
                int c0 = shist[b0], c1 = shist[b0 + 1], c2 = shist[b0 + 2], c3 = shist[b0 + 3];
                int cnt = c0 + c1 + c2 + c3;
                int s = cnt;
#pragma unroll
                for (int off = 1; off < 32; off <<= 1) {
                    int o2 = __shfl_down_sync(0xFFFFFFFFu, s, off);
                    if (lane + off < 32) s += o2;
                }
                if (lane == 0) swtot[wid] = s;
                __syncthreads();
                int above = 0;
#pragma unroll
                for (int w = 0; w < 32; w++)
                    if (w > wid) above += swtot[w];
                int suffix = s + above;
                int cum = suffix - cnt;
                if (cum < krem && suffix >= krem) {
                    int bin;
                    if (cum + c3 >= krem)                bin = b0 + 3;
                    else if (cum + c3 + c2 >= krem)      bin = b0 + 2;
                    else if (cum + c3 + c2 + c1 >= krem) bin = b0 + 1;
                    else                                 bin = b0;
                    s_prefix = prefix | (unsigned)bin;
                }
                __syncthreads();
                prefix = s_prefix;
                __syncthreads();
            }

            // final: sum strictly above threshold + tie fill
            float t = __uint_as_float(prefix);
            double s = 0.0;
            int c = 0;
#pragma unroll 4
            for (int i = tid; i < PP; i += TKT) {
                float x = v[i];
                if (x > t) { s += (double)x; c++; }
            }
            for (int off = 16; off > 0; off >>= 1) {
                s += __shfl_down_sync(0xFFFFFFFFu, s, off);
                c += __shfl_down_sync(0xFFFFFFFFu, c, off);
            }
            __shared__ double sd[32];
            __shared__ int sc[32];
            if (lane == 0) { sd[wid] = s; sc[wid] = c; }
            __syncthreads();
            if (tid == 0) {
                double S = 0.0;
                int C = 0;
                for (int w = 0; w < 32; w++) { S += sd[w]; C += sc[w]; }
                double res = S + (double)(k - C) * (double)t;
                atomicAdd(&g_topk, res);
            }
        }
    }

    // ---- done-counter: last block writes outputs ----
    if (tid == 0) {
        __threadfence();
        int prev = atomicAdd(&g_done, 1);
        if (prev == 319) {
            __threadfence();
            int tp = g_tp;
            double N = tp > 0 ? (double)tp : 1.0;
            out[0] = (float)(g_acc[0] / N);
            out[1] = (float)((g_acc[2] + g_topk) / N);
            out[2] = (float)(g_acc[1] / N);
        }
    }
}

// ---------------- launch ----------------
extern "C" void kernel_launch(void* const* d_in, const int* in_sizes, int n_in,
                              void* d_out, int out_size) {
    const float *loc = nullptr, *conf = nullptr, *landm = nullptr;
    const float *priors = nullptr, *targets = nullptr;
    for (int i = 0; i < n_in; i++) {
        long long s = in_sizes[i];
        if (s == (long long)BB * PP * 4)       loc     = (const float*)d_in[i];
        else if (s == (long long)BB * PP * 3)  conf    = (const float*)d_in[i];
        else if (s == (long long)BB * PP * 10) landm   = (const float*)d_in[i];
        else if (s == (long long)PP * 4)       priors  = (const float*)d_in[i];
        else if (s == (long long)BB * GG * 15) targets = (const float*)d_in[i];
    }

    k_cell<<<128, 256>>>(priors);
    k_ssort<<<128, 256>>>(priors);
    k_match<<<dim3(PP / 1024, BB), 256>>>(targets);
    k_losses<<<dim3(128, BB), 256>>>(conf, targets);
    k_tail<<<320, TKT>>>(loc, conf, landm, priors, targets, (float*)d_out);
}

// round 15
// speedup vs baseline: 1.1215x; 1.0192x over previous
#include <cuda_runtime.h>

#define BB 64
#define PP 32768
#define GG 64

// ---------------- device scratch ----------------
__device__ int    g_cellv[PP];
__device__ int    g_chist[128 * 256];
__device__ float4 g_sppt[PP];     // sorted point-form priors
__device__ float  g_spar[PP];     // sorted areas
__device__ int    g_sidx[PP];     // sorted -> original index
__device__ int    g_btc[BB * PP]; // packed: (best_truth_idx<<1) | (ov>=0.35)
__device__ unsigned long long g_best[BB * GG];
__device__ float  g_lossc[BB * PP];
__device__ int    g_hist1[BB * 256];   // per-batch top-byte histogram
__device__ int    g_poslist[BB * PP];
__device__ int    g_segcnt[BB * 64];   // 64 segments of 512 per batch
__device__ int    g_numpos[BB];
__device__ int    g_tp;
__device__ int    g_done;
__device__ double g_acc[3];
__device__ double g_topk;

__device__ __forceinline__ float sl1(float d) {
    float a = fabsf(d);
    return a < 1.0f ? 0.5f * d * d : a - 0.5f;
}

// ---------------- sort step 1 (+ fused global init) -------------------------
__global__ void __launch_bounds__(256) k_cell(const float* __restrict__ priors) {
    __shared__ int sh[256];
    int tid = threadIdx.x;
    int gt = blockIdx.x * 256 + tid;           // 0..32767
    // fused init
    if (gt < BB * GG) g_best[gt] = 0x00000000FFFFFFFFull;  // ratio=0, p=0
    if (gt < BB) g_numpos[gt] = 0;
    if (gt < 3) g_acc[gt] = 0.0;
    if (gt == 3) g_topk = 0.0;
    if (gt == 4) g_tp = 0;
    if (gt == 5) g_done = 0;
    if (gt < BB * 256) g_hist1[gt] = 0;

    sh[tid] = 0;
    __syncthreads();
    float4 pr = ((const float4*)priors)[gt];
    int cx = min(7, max(0, (int)(pr.x * 8.0f)));
    int cy = min(7, max(0, (int)(pr.y * 8.0f)));
    float mwh = fmaxf(pr.z, pr.w);
    int sc = min(3, max(0, (int)((mwh - 0.02f) * 14.2857f)));
    int cell = ((cy * 8 + cx) << 2) | sc;
    g_cellv[gt] = cell;
    atomicAdd(&sh[cell], 1);
    __syncthreads();
    g_chist[blockIdx.x * 256 + tid] = sh[tid];
}

// ---------------- sort step 2: fused scan + rank-stable scatter -------------
__global__ void __launch_bounds__(256) k_ssort(const float* __restrict__ priors) {
    __shared__ int soff[256];
    __shared__ int sscan[256];
    __shared__ int scnt[8][256];
    int tid = threadIdx.x, lane = tid & 31, wid = tid >> 5;

    int mytot = 0, mypre = 0;
    int myck = blockIdx.x;
#pragma unroll 8
    for (int ch = 0; ch < 128; ch++) {
        int v = g_chist[ch * 256 + tid];
        mytot += v;
        if (ch < myck) mypre += v;
    }
    sscan[tid] = mytot;
    __syncthreads();
    for (int off = 1; off < 256; off <<= 1) {
        int v = (tid >= off) ? sscan[tid - off] : 0;
        __syncthreads();
        sscan[tid] += v;
        __syncthreads();
    }
    soff[tid] = sscan[tid] - mytot + mypre;
#pragma unroll
    for (int i = 0; i < 8; i++) scnt[i][tid] = 0;
    __syncthreads();

    int p = blockIdx.x * 256 + tid;
    int cell = g_cellv[p];
    atomicAdd(&scnt[wid][cell], 1);
    unsigned mk = __match_any_sync(0xFFFFFFFFu, cell);
    int rank = __popc(mk & ((1u << lane) - 1));
    __syncthreads();
    int before = 0;
    for (int w = 0; w < wid; w++) before += scnt[w][cell];
    int slot = soff[cell] + before + rank;

    float4 pr = ((const float4*)priors)[p];
    float4 pt = make_float4(pr.x - pr.z * 0.5f, pr.y - pr.w * 0.5f,
                            pr.x + pr.z * 0.5f, pr.y + pr.w * 0.5f);
    g_sppt[slot] = pt;
    g_spar[slot] = (pt.z - pt.x) * (pt.w - pt.y);
    g_sidx[slot] = p;
}

// ---------------- fused match: one culled pass ----------------
__global__ void __launch_bounds__(256) k_match(const float* __restrict__ targets) {
    __shared__ float sgx1[GG], sgy1[GG], sgx2[GG], sgy2[GG], sga[GG];
    __shared__ float s_r[8][GG];
    __shared__ int   s_ix[8][GG];

    int b = blockIdx.y, tid = threadIdx.x;
    int lane = tid & 31, wid = tid >> 5;

    if (tid < GG) {
        const float* t = targets + ((size_t)b * GG + tid) * 15;
        float x1 = t[0], y1 = t[1], x2 = t[2], y2 = t[3];
        sgx1[tid] = x1; sgy1[tid] = y1; sgx2[tid] = x2; sgy2[tid] = y2;
        sga[tid] = (x2 - x1) * (y2 - y1);
    }
    for (int i = tid; i < 8 * GG; i += 256) {
        ((float*)s_r)[i] = 0.0f;
        ((int*)s_ix)[i] = 0x7FFFFFFF;
    }
    __syncthreads();

    int s0 = blockIdx.x * 1024 + wid * 128 + lane;
    float4 q[4]; float qa[4]; int qi[4];
#pragma unroll
    for (int k = 0; k < 4; k++) {
        q[k] = g_sppt[s0 + 32 * k];
        qa[k] = g_spar[s0 + 32 * k];
        qi[k] = g_sidx[s0 + 32 * k];
    }
    // warp bbox over its 128 priors
    float bx1 = q[0].x, by1 = q[0].y, bx2 = q[0].z, by2 = q[0].w;
#pragma unroll
    for (int k = 1; k < 4; k++) {
        bx1 = fminf(bx1, q[k].x); by1 = fminf(by1, q[k].y);
        bx2 = fmaxf(bx2, q[k].z); by2 = fmaxf(by2, q[k].w);
    }
#pragma unroll
    for (int off = 16; off > 0; off >>= 1) {
        bx1 = fminf(bx1, __shfl_xor_sync(0xFFFFFFFFu, bx1, off));
        by1 = fminf(by1, __shfl_xor_sync(0xFFFFFFFFu, by1, off));
        bx2 = fmaxf(bx2, __shfl_xor_sync(0xFFFFFFFFu, bx2, off));
        by2 = fmaxf(by2, __shfl_xor_sync(0xFFFFFFFFu, by2, off));
    }

    // 64-bit GT hit mask
    bool h0 = sgx1[lane] < bx2 && sgx2[lane] > bx1 &&
              sgy1[lane] < by2 && sgy2[lane] > by1;
    bool h1 = sgx1[lane + 32] < bx2 && sgx2[lane + 32] > bx1 &&
              sgy1[lane + 32] < by2 && sgy2[lane + 32] > by1;
    unsigned m0 = __ballot_sync(0xFFFFFFFFu, h0);
    unsigned m1 = __ballot_sync(0xFFFFFFFFu, h1);
    unsigned long long mask =
        (unsigned long long)m0 | ((unsigned long long)m1 << 32);

    float bin[4], bun[4]; int bix[4];
#pragma unroll
    for (int k = 0; k < 4; k++) { bin[k] = 0.0f; bun[k] = 1.0f; bix[k] = 0; }

    while (mask) {
        int g = __ffsll((long long)mask) - 1;
        mask &= mask - 1;
        float x1 = sgx1[g], y1 = sgy1[g], x2 = sgx2[g], y2 = sgy2[g];
        float ar = sga[g];
        float ti[4], tu[4];
#pragma unroll
        for (int k = 0; k < 4; k++) {
            float lx = fmaxf(x1, q[k].x), ly = fmaxf(y1, q[k].y);
            float rx = fminf(x2, q[k].z), ry = fminf(y2, q[k].w);
            float w = fmaxf(rx - lx, 0.0f), h = fmaxf(ry - ly, 0.0f);
            float inter = w * h;
            float un = (ar + qa[k]) - inter;
            ti[k] = inter; tu[k] = un;
            if (inter * bun[k] > bin[k] * un) { bin[k] = inter; bun[k] = un; bix[k] = g; }
        }
        // local 4-way merge (cross-mult, keep-self on tie)
        float ri = ti[0], ru = tu[0]; int rp = qi[0];
#pragma unroll
        for (int k = 1; k < 4; k++)
            if (ti[k] * ru > ri * tu[k]) { ri = ti[k]; ru = tu[k]; rp = qi[k]; }
        // collapse to ratio; REDUX-based warp argmax
        float r = __fdividef(ri, ru);
        unsigned rb = __float_as_uint(r);          // r >= 0: bits monotone
        unsigned rmax = __reduce_max_sync(0xFFFFFFFFu, rb);
        if (rmax != 0u) {
            unsigned who = __ballot_sync(0xFFFFFFFFu, rb == rmax);
            int src = __ffs(who) - 1;
            int wp = __shfl_sync(0xFFFFFFFFu, rp, src);
            if (lane == 0) {
                s_r[wid][g] = __uint_as_float(rmax);
                s_ix[wid][g] = wp;
            }
        }
    }

    // per-prior results: packed (idx<<1)|thresh, 4B scatter stores
#pragma unroll
    for (int k = 0; k < 4; k++) {
        int flag = (bin[k] >= 0.35f * bun[k]) ? 1 : 0;
        g_btc[(size_t)b * PP + qi[k]] = (bix[k] << 1) | flag;
    }

    __syncthreads();
    // block merge per g + global atomic merge
    if (tid < GG) {
        float r = s_r[0][tid]; int rp = s_ix[0][tid];
#pragma unroll
        for (int w = 1; w < 8; w++) {
            float orr = s_r[w][tid]; int op = s_ix[w][tid];
            if (orr > r || (orr == r && op < rp)) { r = orr; rp = op; }
        }
        if (rp != 0x7FFFFFFF) {
            unsigned long long key =
                ((unsigned long long)__float_as_uint(r) << 32) |
                (unsigned)(~(unsigned)rp);
            atomicMax(&g_best[b * GG + tid], key);
        }
    }
}

// ---------------- loss_c + inline scatter + pos compaction + hist ----------
// 512 threads, window = 512 priors, 64 blocks per batch
__global__ void __launch_bounds__(512) k_losses(const float* __restrict__ conf_data,
                                                const float* __restrict__ targets) {
    __shared__ int shist[256];
    __shared__ int s_og[512];   // override g per in-window prior (atomicMax)
    __shared__ int s_ov[512];   // override valid OR
    __shared__ int s_av;
    __shared__ int s_cnt;
    int b = blockIdx.y, tid = threadIdx.x;
    int lane = tid & 31;
    if (tid < 256) shist[tid] = 0;
    s_og[tid] = -1;
    s_ov[tid] = 0;
    if (tid == 0) { s_av = 0; s_cnt = 0; }
    __syncthreads();

    int pbase = blockIdx.x * 512;
    if (tid < GG) {
        unsigned long long key = g_best[b * GG + tid];
        int pg = (int)(~(unsigned)(key & 0xFFFFFFFFull));
        float ratio = __uint_as_float((unsigned)(key >> 32));
        int valid = ratio >= 0.2f ? 1 : 0;
        if (valid) s_av = 1;                     // benign race, same value
        int loc = pg - pbase;
        if (loc >= 0 && loc < 512) {
            atomicMax(&s_og[loc], tid);          // last-wins: highest g
            if (valid) atomicOr(&s_ov[loc], 1);
        }
    }
    __syncthreads();

    int p = pbase + tid;
    size_t o = (size_t)b * PP + p;
    int packed = g_btc[o];
    int g = packed >> 1;
    int flag = packed & 1;
    if (s_og[tid] >= 0) {
        g = s_og[tid];
        flag |= s_ov[tid];
        g_btc[o] = (g << 1) | flag;              // write-back for tail pos path
    }

    int conf = 0;
    if (s_av && flag)
        conf = (int)__ldg(&targets[((size_t)b * GG + g) * 15 + 14]);

    const float* cd = conf_data + o * 3;
    float c0 = cd[0], c1 = cd[1], c2 = cd[2];
    float mx = fmaxf(c0, fmaxf(c1, c2));
    float lse = mx + __logf(__expf(c0 - mx) + __expf(c1 - mx) + __expf(c2 - mx));
    float gathered = (conf == 0) ? c0 : ((conf == 1) ? c1 : c2);
    float lcv = lse - gathered;
    bool pos = conf > 0;
    float stored = pos ? 0.0f : lcv;
    g_lossc[o] = stored;

    atomicAdd(&shist[__float_as_uint(stored) >> 24], 1);

    // atomic warp compaction (order within segment is arrival-order)
    unsigned m = __ballot_sync(0xFFFFFFFFu, pos);
    int np = __popc(m);
    int base = 0;
    if (np) {
        if (lane == 0) base = atomicAdd(&s_cnt, np);
        base = __shfl_sync(0xFFFFFFFFu, base, 0);
        if (pos)
            g_poslist[((size_t)b * 64 + blockIdx.x) * 512 + base +
                      __popc(m & ((1u << lane) - 1))] = p;
    }
    __syncthreads();

    if (tid < 256 && shist[tid]) atomicAdd(&g_hist1[b * 256 + tid], shist[tid]);
    if (tid == 0) {
        int c = s_cnt;
        g_segcnt[b * 64 + blockIdx.x] = c;
        if (c) {
            atomicAdd(&g_numpos[b], c);
            atomicAdd(&g_tp, c);
        }
    }
}

// ---------------- fused tail: topk (0-63) + pos (64-191) + final ------------
#define TKT 1024
__global__ void __launch_bounds__(TKT) k_tail(const float* __restrict__ loc_data,
                                              const float* __restrict__ conf_data,
                                              const float* __restrict__ landm_data,
                                              const float* __restrict__ priors,
                                              const float* __restrict__ targets,
                                              float* __restrict__ out) {
    int tid = threadIdx.x, lane = tid & 31, wid = tid >> 5;

    if (blockIdx.x >= 64) {
        // ---- pos path: one segment per warp (4096 warps / 4096 segments) ----
        int seg = (blockIdx.x - 64) * 32 + wid;
        int cnt = g_segcnt[seg];
        int b = seg >> 6;
        size_t segbase = (size_t)seg * 512;
        double dl = 0.0, dlm = 0.0, dcp = 0.0;
        for (int i = lane; i < cnt; i += 32) {
            int p = g_poslist[segbase + i];
            size_t o = (size_t)b * PP + p;
            int g = g_btc[o] >> 1;
            const float* t = targets + ((size_t)b * GG + g) * 15;
            int conf = (int)t[14];

            const float* cd = conf_data + o * 3;
            float c0 = cd[0], c1 = cd[1], c2 = cd[2];
            float mx = fmaxf(c0, fmaxf(c1, c2));
            float lse = mx + __logf(__expf(c0 - mx) + __expf(c1 - mx) + __expf(c2 - mx));
            dcp += (double)(lse - ((conf == 1) ? c1 : c2));

            float4 pr = ((const float4*)priors)[p];
            float dwx = 0.1f * pr.z, dwy = 0.1f * pr.w;
            float m0 = t[0], m1 = t[1], m2 = t[2], m3 = t[3];
            float gcx = ((m0 + m2) * 0.5f - pr.x) / dwx;
            float gcy = ((m1 + m3) * 0.5f - pr.y) / dwy;
            float gw2 = __logf((m2 - m0) / pr.z) * 5.0f;
            float gh2 = __logf((m3 - m1) / pr.w) * 5.0f;
            const float* ld = loc_data + o * 4;
            dl += (double)(sl1(ld[0] - gcx) + sl1(ld[1] - gcy) +
                           sl1(ld[2] - gw2) + sl1(ld[3] - gh2));

            const float* lt = t + 4;
            const float* lm = landm_data + o * 10;
            int nd = (conf == 1) ? 10 : 4;
            float s = 0.0f;
            for (int j = 0; j < nd; j += 2) {
                float lx = (lt[j] - pr.x) / dwx;
                float ly = (lt[j + 1] - pr.y) / dwy;
                s += sl1(lm[j] - lx) + sl1(lm[j + 1] - ly);
            }
            dlm += (double)s;
        }
#pragma unroll
        for (int off = 16; off > 0; off >>= 1) {
            dl  += __shfl_down_sync(0xFFFFFFFFu, dl, off);
            dlm += __shfl_down_sync(0xFFFFFFFFu, dlm, off);
            dcp += __shfl_down_sync(0xFFFFFFFFu, dcp, off);
        }
        __shared__ double sdp[3][32];
        if (lane == 0) { sdp[0][wid] = dl; sdp[1][wid] = dlm; sdp[2][wid] = dcp; }
        __syncthreads();
        if (tid == 0) {
            double a = 0, b2 = 0, c = 0;
#pragma unroll
            for (int w = 0; w < 32; w++) { a += sdp[0][w]; b2 += sdp[1][w]; c += sdp[2][w]; }
            if (a != 0.0 || b2 != 0.0 || c != 0.0) {
                atomicAdd(&g_acc[0], a);
                atomicAdd(&g_acc[1], b2);
                atomicAdd(&g_acc[2], c);
            }
        }
    } else {
        // ---- topk path ----
        int b = blockIdx.x;
        int np = g_numpos[b];
        long long kk = 7LL * np;
        if (kk > PP - 1) kk = PP - 1;
        if (kk > 0) {
            int k = (int)kk;
            const float* v = g_lossc + (size_t)b * PP;

            __shared__ int shist[4096];
            __shared__ int swtot[32];
            __shared__ unsigned s_prefix;
            __shared__ int s_krem;

            int krem = k;
            unsigned prefix;

            // pass 1: top byte from precomputed g_hist1
            {
                int cnt = (tid < 256) ? g_hist1[b * 256 + tid] : 0;
                int s = cnt;
#pragma unroll
                for (int off = 1; off < 32; off <<= 1) {
                    int o2 = __shfl_down_sync(0xFFFFFFFFu, s, off);
                    if (lane + off < 32) s += o2;
                }
                if (lane == 0) swtot[wid] = s;
                __syncthreads();
                if (tid < 256) {
                    int above = 0;
#pragma unroll
                    for (int w = 0; w < 8; w++)
                        if (w > wid) above += swtot[w];
                    int suffix = s + above;
                    if (suffix >= krem && suffix - cnt < krem) {
                        s_prefix = (unsigned)tid << 24;
                        s_krem = krem - (suffix - cnt);
                    }
                }
                __syncthreads();
                prefix = s_prefix;
                krem = s_krem;
                __syncthreads();
            }

            // pass 2: bits 23..12
            for (int i = tid; i < 4096; i += TKT) shist[i] = 0;
            __syncthreads();
#pragma unroll 4
            for (int i = tid; i < PP; i += TKT) {
                unsigned u = __float_as_uint(v[i]);
                if ((u & 0xFF000000u) == prefix)
                    atomicAdd(&shist[(u >> 12) & 0xFFFu], 1);
            }
            __syncthreads();
            {
                int b0 = tid * 4;
                int c0 = shist[b0], c1 = shist[b0 + 1], c2 = shist[b0 + 2], c3 = shist[b0 + 3];
                int cnt = c0 + c1 + c2 + c3;
                int s = cnt;
#pragma unroll
                for (int off = 1; off < 32; off <<= 1) {
                    int o2 = __shfl_down_sync(0xFFFFFFFFu, s, off);
                    if (lane + off < 32) s += o2;
                }
                if (lane == 0) swtot[wid] = s;
                __syncthreads();
                int above = 0;
#pragma unroll
                for (int w = 0; w < 32; w++)
                    if (w > wid) above += swtot[w];
                int suffix = s + above;
                int cum = suffix - cnt;
                if (cum < krem && suffix >= krem) {
                    int bin, c;
                    if (cum + c3 >= krem)                { bin = b0 + 3; c = cum; }
                    else if (cum + c3 + c2 >= krem)      { bin = b0 + 2; c = cum + c3; }
                    else if (cum + c3 + c2 + c1 >= krem) { bin = b0 + 1; c = cum + c3 + c2; }
                    else                                 { bin = b0;     c = cum + c3 + c2 + c1; }
                    s_prefix = prefix | ((unsigned)bin << 12);
                    s_krem = krem - c;
                }
                __syncthreads();
                prefix = s_prefix;
                krem = s_krem;
                __syncthreads();
            }

            // pass 3: bits 11..0
            for (int i = tid; i < 4096; i += TKT) shist[i] = 0;
            __syncthreads();
#pragma unroll 4
            for (int i = tid; i < PP; i += TKT) {
                unsigned u = __float_as_uint(v[i]);
                if ((u & 0xFFFFF000u) == prefix)
                    atomicAdd(&shist[u & 0xFFFu], 1);
            }
            __syncthreads();
            {
                int b0 = tid * 4;
                int c0 = shist[b0], c1 = shist[b0 + 1], c2 = shist[b0 + 2], c3 = shist[b0 + 3];
                int cnt = c0 + c1 + c2 + c3;
                int s = cnt;
#pragma unroll
                for (int off = 1; off < 32; off <<= 1) {
                    int o2 = __shfl_down_sync(0xFFFFFFFFu, s, off);
                    if (lane + off < 32) s += o2;
                }
                if (lane == 0) swtot[wid] = s;
                __syncthreads();
                int above = 0;
#pragma unroll
                for (int w = 0; w < 32; w++)
                    if (w > wid) above += swtot[w];
                int suffix = s + above;
                int cum = suffix - cnt;
                if (cum < krem && suffix >= krem) {
                    int bin;
                    if (cum + c3 >= krem)                bin = b0 + 3;
                    else if (cum + c3 + c2 >= krem)      bin = b0 + 2;
                    else if (cum + c3 + c2 + c1 >= krem) bin = b0 + 1;
                    else                                 bin = b0;
                    s_prefix = prefix | (unsigned)bin;
                }
                __syncthreads();
                prefix = s_prefix;
                __syncthreads();
            }

            // final: sum strictly above threshold + tie fill
            float t = __uint_as_float(prefix);
            double s = 0.0;
            int c = 0;
#pragma unroll 4
            for (int i = tid; i < PP; i += TKT) {
                float x = v[i];
                if (x > t) { s += (double)x; c++; }
            }
            for (int off = 16; off > 0; off >>= 1) {
                s += __shfl_down_sync(0xFFFFFFFFu, s, off);
                c += __shfl_down_sync(0xFFFFFFFFu, c, off);
            }
            __shared__ double sd[32];
            __shared__ int sc[32];
            if (lane == 0) { sd[wid] = s; sc[wid] = c; }
            __syncthreads();
            if (tid == 0) {
                double S = 0.0;
                int C = 0;
                for (int w = 0; w < 32; w++) { S += sd[w]; C += sc[w]; }
                double res = S + (double)(k - C) * (double)t;
                atomicAdd(&g_topk, res);
            }
        }
    }

    // ---- done-counter: last block writes outputs ----
    if (tid == 0) {
        __threadfence();
        int prev = atomicAdd(&g_done, 1);
        if (prev == 191) {
            __threadfence();
            int tp = g_tp;
            double N = tp > 0 ? (double)tp : 1.0;
            out[0] = (float)(g_acc[0] / N);
            out[1] = (float)((g_acc[2] + g_topk) / N);
            out[2] = (float)(g_acc[1] / N);
        }
    }
}

// ---------------- launch ----------------
extern "C" void kernel_launch(void* const* d_in, const int* in_sizes, int n_in,
                              void* d_out, int out_size) {
    const float *loc = nullptr, *conf = nullptr, *landm = nullptr;
    const float *priors = nullptr, *targets = nullptr;
    for (int i = 0; i < n_in; i++) {
        long long s = in_sizes[i];
        if (s == (long long)BB * PP * 4)       loc     = (const float*)d_in[i];
        else if (s == (long long)BB * PP * 3)  conf    = (const float*)d_in[i];
        else if (s == (long long)BB * PP * 10) landm   = (const float*)d_in[i];
        else if (s == (long long)PP * 4)       priors  = (const float*)d_in[i];
        else if (s == (long long)BB * GG * 15) targets = (const float*)d_in[i];
    }

    k_cell<<<128, 256>>>(priors);
    k_ssort<<<128, 256>>>(priors);
    k_match<<<dim3(PP / 1024, BB), 256>>>(targets);
    k_losses<<<dim3(64, BB), 512>>>(conf, targets);
    k_tail<<<192, TKT>>>(loc, conf, landm, priors, targets, (float*)d_out);
}

// round 16
// speedup vs baseline: 1.1772x; 1.0497x over previous
#include <cuda_runtime.h>

#define BB 64
#define PP 32768
#define GG 64

// ---------------- device scratch ----------------
__device__ int    g_cellv[PP];
__device__ int    g_chist[128 * 256];
__device__ float4 g_sppt[PP];     // sorted point-form priors
__device__ float  g_spar[PP];     // sorted areas
__device__ int    g_sidx[PP];     // sorted -> original index
__device__ int    g_btc[BB * PP]; // packed: (best_truth_idx<<1) | (ov>=0.35)
__device__ unsigned long long g_best[BB * GG];
__device__ float  g_lossc[BB * PP];
__device__ int    g_hist1[BB * 256];   // per-batch top-byte histogram
__device__ int    g_poslist[BB * PP];
__device__ int    g_segcnt[BB * 32];   // 32 segments of 1024 per batch
__device__ int    g_numpos[BB];
__device__ int    g_tp;
__device__ int    g_done;
__device__ double g_acc[3];
__device__ double g_topk;

__device__ __forceinline__ float sl1(float d) {
    float a = fabsf(d);
    return a < 1.0f ? 0.5f * d * d : a - 0.5f;
}

// ---------------- sort step 1 (+ fused global init) -------------------------
__global__ void __launch_bounds__(256) k_cell(const float* __restrict__ priors) {
    __shared__ int sh[256];
    int tid = threadIdx.x;
    int gt = blockIdx.x * 256 + tid;           // 0..32767
    // fused init
    if (gt < BB * GG) g_best[gt] = 0x00000000FFFFFFFFull;  // ratio=0, p=0
    if (gt < BB) g_numpos[gt] = 0;
    if (gt < 3) g_acc[gt] = 0.0;
    if (gt == 3) g_topk = 0.0;
    if (gt == 4) g_tp = 0;
    if (gt == 5) g_done = 0;
    if (gt < BB * 256) g_hist1[gt] = 0;

    sh[tid] = 0;
    __syncthreads();
    float4 pr = ((const float4*)priors)[gt];
    int cx = min(7, max(0, (int)(pr.x * 8.0f)));
    int cy = min(7, max(0, (int)(pr.y * 8.0f)));
    float mwh = fmaxf(pr.z, pr.w);
    int sc = min(3, max(0, (int)((mwh - 0.02f) * 14.2857f)));
    int cell = ((cy * 8 + cx) << 2) | sc;
    g_cellv[gt] = cell;
    atomicAdd(&sh[cell], 1);
    __syncthreads();
    g_chist[blockIdx.x * 256 + tid] = sh[tid];
}

// ---------------- sort step 2: fused scan + rank-stable scatter -------------
__global__ void __launch_bounds__(256) k_ssort(const float* __restrict__ priors) {
    __shared__ int soff[256];
    __shared__ int sscan[256];
    __shared__ int scnt[8][256];
    int tid = threadIdx.x, lane = tid & 31, wid = tid >> 5;

    int mytot = 0, mypre = 0;
    int myck = blockIdx.x;
#pragma unroll 8
    for (int ch = 0; ch < 128; ch++) {
        int v = g_chist[ch * 256 + tid];
        mytot += v;
        if (ch < myck) mypre += v;
    }
    sscan[tid] = mytot;
    __syncthreads();
    for (int off = 1; off < 256; off <<= 1) {
        int v = (tid >= off) ? sscan[tid - off] : 0;
        __syncthreads();
        sscan[tid] += v;
        __syncthreads();
    }
    soff[tid] = sscan[tid] - mytot + mypre;
#pragma unroll
    for (int i = 0; i < 8; i++) scnt[i][tid] = 0;
    __syncthreads();

    int p = blockIdx.x * 256 + tid;
    int cell = g_cellv[p];
    atomicAdd(&scnt[wid][cell], 1);
    unsigned mk = __match_any_sync(0xFFFFFFFFu, cell);
    int rank = __popc(mk & ((1u << lane) - 1));
    __syncthreads();
    int before = 0;
    for (int w = 0; w < wid; w++) before += scnt[w][cell];
    int slot = soff[cell] + before + rank;

    float4 pr = ((const float4*)priors)[p];
    float4 pt = make_float4(pr.x - pr.z * 0.5f, pr.y - pr.w * 0.5f,
                            pr.x + pr.z * 0.5f, pr.y + pr.w * 0.5f);
    g_sppt[slot] = pt;
    g_spar[slot] = (pt.z - pt.x) * (pt.w - pt.y);
    g_sidx[slot] = p;
}

// ---------------- fused match: one culled pass ----------------
__global__ void __launch_bounds__(256) k_match(const float* __restrict__ targets) {
    __shared__ float sgx1[GG], sgy1[GG], sgx2[GG], sgy2[GG], sga[GG];
    __shared__ float s_r[8][GG];
    __shared__ int   s_ix[8][GG];

    int b = blockIdx.y, tid = threadIdx.x;
    int lane = tid & 31, wid = tid >> 5;

    if (tid < GG) {
        const float* t = targets + ((size_t)b * GG + tid) * 15;
        float x1 = t[0], y1 = t[1], x2 = t[2], y2 = t[3];
        sgx1[tid] = x1; sgy1[tid] = y1; sgx2[tid] = x2; sgy2[tid] = y2;
        sga[tid] = (x2 - x1) * (y2 - y1);
    }
    for (int i = tid; i < 8 * GG; i += 256) {
        ((float*)s_r)[i] = 0.0f;
        ((int*)s_ix)[i] = 0x7FFFFFFF;
    }
    __syncthreads();

    int s0 = blockIdx.x * 1024 + wid * 128 + lane;
    float4 q[4]; float qa[4]; int qi[4];
#pragma unroll
    for (int k = 0; k < 4; k++) {
        q[k] = g_sppt[s0 + 32 * k];
        qa[k] = g_spar[s0 + 32 * k];
        qi[k] = g_sidx[s0 + 32 * k];
    }
    // warp bbox over its 128 priors
    float bx1 = q[0].x, by1 = q[0].y, bx2 = q[0].z, by2 = q[0].w;
#pragma unroll
    for (int k = 1; k < 4; k++) {
        bx1 = fminf(bx1, q[k].x); by1 = fminf(by1, q[k].y);
        bx2 = fmaxf(bx2, q[k].z); by2 = fmaxf(by2, q[k].w);
    }
#pragma unroll
    for (int off = 16; off > 0; off >>= 1) {
        bx1 = fminf(bx1, __shfl_xor_sync(0xFFFFFFFFu, bx1, off));
        by1 = fminf(by1, __shfl_xor_sync(0xFFFFFFFFu, by1, off));
        bx2 = fmaxf(bx2, __shfl_xor_sync(0xFFFFFFFFu, bx2, off));
        by2 = fmaxf(by2, __shfl_xor_sync(0xFFFFFFFFu, by2, off));
    }

    // 64-bit GT hit mask
    bool h0 = sgx1[lane] < bx2 && sgx2[lane] > bx1 &&
              sgy1[lane] < by2 && sgy2[lane] > by1;
    bool h1 = sgx1[lane + 32] < bx2 && sgx2[lane + 32] > bx1 &&
              sgy1[lane + 32] < by2 && sgy2[lane + 32] > by1;
    unsigned m0 = __ballot_sync(0xFFFFFFFFu, h0);
    unsigned m1 = __ballot_sync(0xFFFFFFFFu, h1);
    unsigned long long mask =
        (unsigned long long)m0 | ((unsigned long long)m1 << 32);

    float bin[4], bun[4]; int bix[4];
#pragma unroll
    for (int k = 0; k < 4; k++) { bin[k] = 0.0f; bun[k] = 1.0f; bix[k] = 0; }

    while (mask) {
        int g = __ffsll((long long)mask) - 1;
        mask &= mask - 1;
        float x1 = sgx1[g], y1 = sgy1[g], x2 = sgx2[g], y2 = sgy2[g];
        float ar = sga[g];
        float ti[4], tu[4];
#pragma unroll
        for (int k = 0; k < 4; k++) {
            float lx = fmaxf(x1, q[k].x), ly = fmaxf(y1, q[k].y);
            float rx = fminf(x2, q[k].z), ry = fminf(y2, q[k].w);
            float w = fmaxf(rx - lx, 0.0f), h = fmaxf(ry - ly, 0.0f);
            float inter = w * h;
            float un = (ar + qa[k]) - inter;
            ti[k] = inter; tu[k] = un;
            if (inter * bun[k] > bin[k] * un) { bin[k] = inter; bun[k] = un; bix[k] = g; }
        }
        // local 4-way merge (cross-mult, keep-self on tie)
        float ri = ti[0], ru = tu[0]; int rp = qi[0];
#pragma unroll
        for (int k = 1; k < 4; k++)
            if (ti[k] * ru > ri * tu[k]) { ri = ti[k]; ru = tu[k]; rp = qi[k]; }
        // collapse to ratio; REDUX-based warp argmax
        float r = __fdividef(ri, ru);
        unsigned rb = __float_as_uint(r);          // r >= 0: bits monotone
        unsigned rmax = __reduce_max_sync(0xFFFFFFFFu, rb);
        if (rmax != 0u) {
            unsigned who = __ballot_sync(0xFFFFFFFFu, rb == rmax);
            int src = __ffs(who) - 1;
            int wp = __shfl_sync(0xFFFFFFFFu, rp, src);
            if (lane == 0) {
                s_r[wid][g] = __uint_as_float(rmax);
                s_ix[wid][g] = wp;
            }
        }
    }

    // per-prior results: packed (idx<<1)|thresh, 4B scatter stores
#pragma unroll
    for (int k = 0; k < 4; k++) {
        int flag = (bin[k] >= 0.35f * bun[k]) ? 1 : 0;
        g_btc[(size_t)b * PP + qi[k]] = (bix[k] << 1) | flag;
    }

    __syncthreads();
    // block merge per g + global atomic merge
    if (tid < GG) {
        float r = s_r[0][tid]; int rp = s_ix[0][tid];
#pragma unroll
        for (int w = 1; w < 8; w++) {
            float orr = s_r[w][tid]; int op = s_ix[w][tid];
            if (orr > r || (orr == r && op < rp)) { r = orr; rp = op; }
        }
        if (rp != 0x7FFFFFFF) {
            unsigned long long key =
                ((unsigned long long)__float_as_uint(r) << 32) |
                (unsigned)(~(unsigned)rp);
            atomicMax(&g_best[b * GG + tid], key);
        }
    }
}

// ---------------- loss_c + inline scatter + pos compaction + hist ----------
// 512 threads, 2 priors/thread, window = 1024 priors, 32 blocks per batch
__global__ void __launch_bounds__(512) k_losses(const float* __restrict__ conf_data,
                                                const float* __restrict__ targets) {
    __shared__ int shist[256];
    __shared__ int s_og[1024];
    __shared__ int s_ov[1024];
    __shared__ int s_av;
    __shared__ int s_cnt;
    int b = blockIdx.y, tid = threadIdx.x;
    int lane = tid & 31;
    if (tid < 256) shist[tid] = 0;
    s_og[tid] = -1; s_og[tid + 512] = -1;
    s_ov[tid] = 0;  s_ov[tid + 512] = 0;
    if (tid == 0) { s_av = 0; s_cnt = 0; }
    __syncthreads();

    int pbase = blockIdx.x * 1024;
    if (tid < GG) {
        unsigned long long key = g_best[b * GG + tid];
        int pg = (int)(~(unsigned)(key & 0xFFFFFFFFull));
        float ratio = __uint_as_float((unsigned)(key >> 32));
        int valid = ratio >= 0.2f ? 1 : 0;
        if (valid) s_av = 1;                     // benign race, same value
        int loc = pg - pbase;
        if (loc >= 0 && loc < 1024) {
            atomicMax(&s_og[loc], tid);          // last-wins: highest g
            if (valid) atomicOr(&s_ov[loc], 1);
        }
    }
    __syncthreads();

    int av = s_av;
    size_t segbase = ((size_t)b * 32 + blockIdx.x) * 1024;

    // two independent prior chains for MLP
#pragma unroll
    for (int half = 0; half < 2; half++) {
        int loc = tid + half * 512;
        int p = pbase + loc;
        size_t o = (size_t)b * PP + p;
        int packed = g_btc[o];
        int g = packed >> 1;
        int flag = packed & 1;
        if (s_og[loc] >= 0) {
            g = s_og[loc];
            flag |= s_ov[loc];
            g_btc[o] = (g << 1) | flag;          // write-back for tail pos path
        }

        int conf = 0;
        if (av && flag)
            conf = (int)__ldg(&targets[((size_t)b * GG + g) * 15 + 14]);

        const float* cd = conf_data + o * 3;
        float c0 = cd[0], c1 = cd[1], c2 = cd[2];
        float mx = fmaxf(c0, fmaxf(c1, c2));
        float lse = mx + __logf(__expf(c0 - mx) + __expf(c1 - mx) + __expf(c2 - mx));
        float gathered = (conf == 0) ? c0 : ((conf == 1) ? c1 : c2);
        float lcv = lse - gathered;
        bool pos = conf > 0;
        float stored = pos ? 0.0f : lcv;
        g_lossc[o] = stored;

        atomicAdd(&shist[__float_as_uint(stored) >> 24], 1);

        unsigned m = __ballot_sync(0xFFFFFFFFu, pos);
        int np = __popc(m);
        if (np) {
            int base = 0;
            if (lane == 0) base = atomicAdd(&s_cnt, np);
            base = __shfl_sync(0xFFFFFFFFu, base, 0);
            if (pos)
                g_poslist[segbase + base + __popc(m & ((1u << lane) - 1))] = p;
        }
    }
    __syncthreads();

    if (tid < 256 && shist[tid]) atomicAdd(&g_hist1[b * 256 + tid], shist[tid]);
    if (tid == 0) {
        int c = s_cnt;
        g_segcnt[b * 32 + blockIdx.x] = c;
        if (c) {
            atomicAdd(&g_numpos[b], c);
            atomicAdd(&g_tp, c);
        }
    }
}

// ---------------- fused tail: topk (0-63) + pos (64-127) + final ------------
#define TKT 1024
__global__ void __launch_bounds__(TKT) k_tail(const float* __restrict__ loc_data,
                                              const float* __restrict__ conf_data,
                                              const float* __restrict__ landm_data,
                                              const float* __restrict__ priors,
                                              const float* __restrict__ targets,
                                              float* __restrict__ out) {
    int tid = threadIdx.x, lane = tid & 31, wid = tid >> 5;

    if (blockIdx.x >= 64) {
        // ---- pos path: one segment per warp (2048 warps / 2048 segments) ----
        int seg = (blockIdx.x - 64) * 32 + wid;
        int cnt = g_segcnt[seg];
        int b = seg >> 5;
        size_t segbase = (size_t)seg * 1024;
        double dl = 0.0, dlm = 0.0, dcp = 0.0;
        for (int i = lane; i < cnt; i += 32) {
            int p = g_poslist[segbase + i];
            size_t o = (size_t)b * PP + p;
            int g = g_btc[o] >> 1;
            const float* t = targets + ((size_t)b * GG + g) * 15;
            int conf = (int)t[14];

            const float* cd = conf_data + o * 3;
            float c0 = cd[0], c1 = cd[1], c2 = cd[2];
            float mx = fmaxf(c0, fmaxf(c1, c2));
            float lse = mx + __logf(__expf(c0 - mx) + __expf(c1 - mx) + __expf(c2 - mx));
            dcp += (double)(lse - ((conf == 1) ? c1 : c2));

            float4 pr = ((const float4*)priors)[p];
            float dwx = 0.1f * pr.z, dwy = 0.1f * pr.w;
            float m0 = t[0], m1 = t[1], m2 = t[2], m3 = t[3];
            float gcx = ((m0 + m2) * 0.5f - pr.x) / dwx;
            float gcy = ((m1 + m3) * 0.5f - pr.y) / dwy;
            float gw2 = __logf((m2 - m0) / pr.z) * 5.0f;
            float gh2 = __logf((m3 - m1) / pr.w) * 5.0f;
            const float* ld = loc_data + o * 4;
            dl += (double)(sl1(ld[0] - gcx) + sl1(ld[1] - gcy) +
                           sl1(ld[2] - gw2) + sl1(ld[3] - gh2));

            const float* lt = t + 4;
            const float* lm = landm_data + o * 10;
            int nd = (conf == 1) ? 10 : 4;
            float s = 0.0f;
            for (int j = 0; j < nd; j += 2) {
                float lx = (lt[j] - pr.x) / dwx;
                float ly = (lt[j + 1] - pr.y) / dwy;
                s += sl1(lm[j] - lx) + sl1(lm[j + 1] - ly);
            }
            dlm += (double)s;
        }
#pragma unroll
        for (int off = 16; off > 0; off >>= 1) {
            dl  += __shfl_down_sync(0xFFFFFFFFu, dl, off);
            dlm += __shfl_down_sync(0xFFFFFFFFu, dlm, off);
            dcp += __shfl_down_sync(0xFFFFFFFFu, dcp, off);
        }
        __shared__ double sdp[3][32];
        if (lane == 0) { sdp[0][wid] = dl; sdp[1][wid] = dlm; sdp[2][wid] = dcp; }
        __syncthreads();
        if (tid == 0) {
            double a = 0, b2 = 0, c = 0;
#pragma unroll
            for (int w = 0; w < 32; w++) { a += sdp[0][w]; b2 += sdp[1][w]; c += sdp[2][w]; }
            if (a != 0.0 || b2 != 0.0 || c != 0.0) {
                atomicAdd(&g_acc[0], a);
                atomicAdd(&g_acc[1], b2);
                atomicAdd(&g_acc[2], c);
            }
        }
    } else {
        // ---- topk path ----
        int b = blockIdx.x;
        int np = g_numpos[b];
        long long kk = 7LL * np;
        if (kk > PP - 1) kk = PP - 1;
        if (kk > 0) {
            int k = (int)kk;
            const float* v = g_lossc + (size_t)b * PP;

            __shared__ int shist[4096];
            __shared__ int swtot[32];
            __shared__ unsigned s_prefix;
            __shared__ int s_krem;

            int krem = k;
            unsigned prefix;

            // pass 1: top byte from precomputed g_hist1
            {
                int cnt = (tid < 256) ? g_hist1[b * 256 + tid] : 0;
                int s = cnt;
#pragma unroll
                for (int off = 1; off < 32; off <<= 1) {
                    int o2 = __shfl_down_sync(0xFFFFFFFFu, s, off);
                    if (lane + off < 32) s += o2;
                }
                if (lane == 0) swtot[wid] = s;
                __syncthreads();
                if (tid < 256) {
                    int above = 0;
#pragma unroll
                    for (int w = 0; w < 8; w++)
                        if (w > wid) above += swtot[w];
                    int suffix = s + above;
                    if (suffix >= krem && suffix - cnt < krem) {
                        s_prefix = (unsigned)tid << 24;
                        s_krem = krem - (suffix - cnt);
                    }
                }
                __syncthreads();
                prefix = s_prefix;
                krem = s_krem;
                __syncthreads();
            }

            // pass 2: bits 23..12
            for (int i = tid; i < 4096; i += TKT) shist[i] = 0;
            __syncthreads();
#pragma unroll 4
            for (int i = tid; i < PP; i += TKT) {
                unsigned u = __float_as_uint(v[i]);
                if ((u & 0xFF000000u) == prefix)
                    atomicAdd(&shist[(u >> 12) & 0xFFFu], 1);
            }
            __syncthreads();
            {
                int b0 = tid * 4;
                int c0 = shist[b0], c1 = shist[b0 + 1], c2 = shist[b0 + 2], c3 = shist[b0 + 3];
                int cnt = c0 + c1 + c2 + c3;
                int s = cnt;
#pragma unroll
                for (int off = 1; off < 32; off <<= 1) {
                    int o2 = __shfl_down_sync(0xFFFFFFFFu, s, off);
                    if (lane + off < 32) s += o2;
                }
                if (lane == 0) swtot[wid] = s;
                __syncthreads();
                int above = 0;
#pragma unroll
                for (int w = 0; w < 32; w++)
                    if (w > wid) above += swtot[w];
                int suffix = s + above;
                int cum = suffix - cnt;
                if (cum < krem && suffix >= krem) {
                    int bin, c;
                    if (cum + c3 >= krem)                { bin = b0 + 3; c = cum; }
                    else if (cum + c3 + c2 >= krem)      { bin = b0 + 2; c = cum + c3; }
                    else if (cum + c3 + c2 + c1 >= krem) { bin = b0 + 1; c = cum + c3 + c2; }
                    else                                 { bin = b0;     c = cum + c3 + c2 + c1; }
                    s_prefix = prefix | ((unsigned)bin << 12);
                    s_krem = krem - c;
                }
                __syncthreads();
                prefix = s_prefix;
                krem = s_krem;
                __syncthreads();
            }

            // pass 3: bits 11..0
            for (int i = tid; i < 4096; i += TKT) shist[i] = 0;
            __syncthreads();
#pragma unroll 4
            for (int i = tid; i < PP; i += TKT) {
                unsigned u = __float_as_uint(v[i]);
                if ((u & 0xFFFFF000u) == prefix)
                    atomicAdd(&shist[u & 0xFFFu], 1);
            }
            __syncthreads();
            {
                int b0 = tid * 4;
                int c0 = shist[b0], c1 = shist[b0 + 1], c2 = shist[b0 + 2], c3 = shist[b0 + 3];
                int cnt = c0 + c1 + c2 + c3;
                int s = cnt;
#pragma unroll
                for (int off = 1; off < 32; off <<= 1) {
                    int o2 = __shfl_down_sync(0xFFFFFFFFu, s, off);
                    if (lane + off < 32) s += o2;
                }
                if (lane == 0) swtot[wid] = s;
                __syncthreads();
                int above = 0;
#pragma unroll
                for (int w = 0; w < 32; w++)
                    if (w > wid) above += swtot[w];
                int suffix = s + above;
                int cum = suffix - cnt;
                if (cum < krem && suffix >= krem) {
                    int bin;
                    if (cum + c3 >= krem)                bin = b0 + 3;
                    else if (cum + c3 + c2 >= krem)      bin = b0 + 2;
                    else if (cum + c3 + c2 + c1 >= krem) bin = b0 + 1;
                    else                                 bin = b0;
                    s_prefix = prefix | (unsigned)bin;
                }
                __syncthreads();
                prefix = s_prefix;
                __syncthreads();
            }

            // final: sum strictly above threshold + tie fill
            float t = __uint_as_float(prefix);
            double s = 0.0;
            int c = 0;
#pragma unroll 4
            for (int i = tid; i < PP; i += TKT) {
                float x = v[i];
                if (x > t) { s += (double)x; c++; }
            }
            for (int off = 16; off > 0; off >>= 1) {
                s += __shfl_down_sync(0xFFFFFFFFu, s, off);
                c += __shfl_down_sync(0xFFFFFFFFu, c, off);
            }
            __shared__ double sd[32];
            __shared__ int sc[32];
            if (lane == 0) { sd[wid] = s; sc[wid] = c; }
            __syncthreads();
            if (tid == 0) {
                double S = 0.0;
                int C = 0;
                for (int w = 0; w < 32; w++) { S += sd[w]; C += sc[w]; }
                double res = S + (double)(k - C) * (double)t;
                atomicAdd(&g_topk, res);
            }
        }
    }

    // ---- done-counter: last block writes outputs ----
    if (tid == 0) {
        __threadfence();
        int prev = atomicAdd(&g_done, 1);
        if (prev == 127) {
            __threadfence();
            int tp = g_tp;
            double N = tp > 0 ? (double)tp : 1.0;
            out[0] = (float)(g_acc[0] / N);
            out[1] = (float)((g_acc[2] + g_topk) / N);
            out[2] = (float)(g_acc[1] / N);
        }
    }
}

// ---------------- launch ----------------
extern "C" void kernel_launch(void* const* d_in, const int* in_sizes, int n_in,
                              void* d_out, int out_size) {
    const float *loc = nullptr, *conf = nullptr, *landm = nullptr;
    const float *priors = nullptr, *targets = nullptr;
    for (int i = 0; i < n_in; i++) {
        long long s = in_sizes[i];
        if (s == (long long)BB * PP * 4)       loc     = (const float*)d_in[i];
        else if (s == (long long)BB * PP * 3)  conf    = (const float*)d_in[i];
        else if (s == (long long)BB * PP * 10) landm   = (const float*)d_in[i];
        else if (s == (long long)PP * 4)       priors  = (const float*)d_in[i];
        else if (s == (long long)BB * GG * 15) targets = (const float*)d_in[i];
    }

    k_cell<<<128, 256>>>(priors);
    k_ssort<<<128, 256>>>(priors);
    k_match<<<dim3(PP / 1024, BB), 256>>>(targets);
    k_losses<<<dim3(32, BB), 512>>>(conf, targets);
    k_tail<<<128, TKT>>>(loc, conf, landm, priors, targets, (float*)d_out);
}

// round 17
// speedup vs baseline: 1.1775x; 1.0003x over previous
#include <cuda_runtime.h>

#define BB 64
#define PP 32768
#define GG 64

// ---------------- device scratch ----------------
__device__ int    g_cellv[PP];
__device__ int    g_chist[128 * 256];
__device__ float4 g_sppt[PP];     // sorted point-form priors
__device__ float  g_spar[PP];     // sorted areas
__device__ int    g_sidx[PP];     // sorted -> original index
__device__ int    g_btc[BB * PP]; // packed: (best_truth_idx<<1) | (ov>=0.35)
__device__ unsigned long long g_best[BB * GG];
__device__ float  g_lossc[BB * PP];
__device__ int    g_hist1[BB * 256];   // per-batch top-byte histogram
__device__ int    g_poslist[BB * PP];
__device__ int    g_segcnt[BB * 32];   // 32 segments of 1024 per batch
__device__ int    g_numpos[BB];
__device__ int    g_tp;
__device__ int    g_done;
__device__ double g_acc[3];
__device__ double g_topk;

__device__ __forceinline__ float sl1(float d) {
    float a = fabsf(d);
    return a < 1.0f ? 0.5f * d * d : a - 0.5f;
}

// ---------------- sort step 1 (+ fused global init) -------------------------
__global__ void __launch_bounds__(256) k_cell(const float* __restrict__ priors) {
    __shared__ int sh[256];
    int tid = threadIdx.x;
    int gt = blockIdx.x * 256 + tid;           // 0..32767
    // fused init
    if (gt < BB * GG) g_best[gt] = 0x00000000FFFFFFFFull;  // ratio=0, p=0
    if (gt < BB) g_numpos[gt] = 0;
    if (gt < 3) g_acc[gt] = 0.0;
    if (gt == 3) g_topk = 0.0;
    if (gt == 4) g_tp = 0;
    if (gt == 5) g_done = 0;
    if (gt < BB * 256) g_hist1[gt] = 0;

    sh[tid] = 0;
    __syncthreads();
    float4 pr = ((const float4*)priors)[gt];
    int cx = min(7, max(0, (int)(pr.x * 8.0f)));
    int cy = min(7, max(0, (int)(pr.y * 8.0f)));
    float mwh = fmaxf(pr.z, pr.w);
    int sc = min(3, max(0, (int)((mwh - 0.02f) * 14.2857f)));
    int cell = ((cy * 8 + cx) << 2) | sc;
    g_cellv[gt] = cell;
    atomicAdd(&sh[cell], 1);
    __syncthreads();
    g_chist[blockIdx.x * 256 + tid] = sh[tid];
}

// ---------------- sort step 2: fused scan + rank-stable scatter -------------
__global__ void __launch_bounds__(256) k_ssort(const float* __restrict__ priors) {
    __shared__ int soff[256];
    __shared__ int sscan[256];
    __shared__ int scnt[8][256];
    int tid = threadIdx.x, lane = tid & 31, wid = tid >> 5;

    int mytot = 0, mypre = 0;
    int myck = blockIdx.x;
#pragma unroll 8
    for (int ch = 0; ch < 128; ch++) {
        int v = g_chist[ch * 256 + tid];
        mytot += v;
        if (ch < myck) mypre += v;
    }
    sscan[tid] = mytot;
    __syncthreads();
    for (int off = 1; off < 256; off <<= 1) {
        int v = (tid >= off) ? sscan[tid - off] : 0;
        __syncthreads();
        sscan[tid] += v;
        __syncthreads();
    }
    soff[tid] = sscan[tid] - mytot + mypre;
#pragma unroll
    for (int i = 0; i < 8; i++) scnt[i][tid] = 0;
    __syncthreads();

    int p = blockIdx.x * 256 + tid;
    int cell = g_cellv[p];
    atomicAdd(&scnt[wid][cell], 1);
    unsigned mk = __match_any_sync(0xFFFFFFFFu, cell);
    int rank = __popc(mk & ((1u << lane) - 1));
    __syncthreads();
    int before = 0;
    for (int w = 0; w < wid; w++) before += scnt[w][cell];
    int slot = soff[cell] + before + rank;

    float4 pr = ((const float4*)priors)[p];
    float4 pt = make_float4(pr.x - pr.z * 0.5f, pr.y - pr.w * 0.5f,
                            pr.x + pr.z * 0.5f, pr.y + pr.w * 0.5f);
    g_sppt[slot] = pt;
    g_spar[slot] = (pt.z - pt.x) * (pt.w - pt.y);
    g_sidx[slot] = p;
}

// ---------------- fused match: one culled pass ----------------
__global__ void __launch_bounds__(256) k_match(const float* __restrict__ targets) {
    __shared__ float sgx1[GG], sgy1[GG], sgx2[GG], sgy2[GG], sga[GG];
    __shared__ float s_r[8][GG];
    __shared__ int   s_ix[8][GG];

    int b = blockIdx.y, tid = threadIdx.x;
    int lane = tid & 31, wid = tid >> 5;

    if (tid < GG) {
        const float* t = targets + ((size_t)b * GG + tid) * 15;
        float x1 = t[0], y1 = t[1], x2 = t[2], y2 = t[3];
        sgx1[tid] = x1; sgy1[tid] = y1; sgx2[tid] = x2; sgy2[tid] = y2;
        sga[tid] = (x2 - x1) * (y2 - y1);
    }
    for (int i = tid; i < 8 * GG; i += 256) {
        ((float*)s_r)[i] = 0.0f;
        ((int*)s_ix)[i] = 0x7FFFFFFF;
    }
    __syncthreads();

    int s0 = blockIdx.x * 1024 + wid * 128 + lane;
    float4 q[4]; float qa[4]; int qi[4];
#pragma unroll
    for (int k = 0; k < 4; k++) {
        q[k] = g_sppt[s0 + 32 * k];
        qa[k] = g_spar[s0 + 32 * k];
        qi[k] = g_sidx[s0 + 32 * k];
    }
    // warp bbox over its 128 priors
    float bx1 = q[0].x, by1 = q[0].y, bx2 = q[0].z, by2 = q[0].w;
#pragma unroll
    for (int k = 1; k < 4; k++) {
        bx1 = fminf(bx1, q[k].x); by1 = fminf(by1, q[k].y);
        bx2 = fmaxf(bx2, q[k].z); by2 = fmaxf(by2, q[k].w);
    }
#pragma unroll
    for (int off = 16; off > 0; off >>= 1) {
        bx1 = fminf(bx1, __shfl_xor_sync(0xFFFFFFFFu, bx1, off));
        by1 = fminf(by1, __shfl_xor_sync(0xFFFFFFFFu, by1, off));
        bx2 = fmaxf(bx2, __shfl_xor_sync(0xFFFFFFFFu, bx2, off));
        by2 = fmaxf(by2, __shfl_xor_sync(0xFFFFFFFFu, by2, off));
    }

    // 64-bit GT hit mask
    bool h0 = sgx1[lane] < bx2 && sgx2[lane] > bx1 &&
              sgy1[lane] < by2 && sgy2[lane] > by1;
    bool h1 = sgx1[lane + 32] < bx2 && sgx2[lane + 32] > bx1 &&
              sgy1[lane + 32] < by2 && sgy2[lane + 32] > by1;
    unsigned m0 = __ballot_sync(0xFFFFFFFFu, h0);
    unsigned m1 = __ballot_sync(0xFFFFFFFFu, h1);
    unsigned long long mask =
        (unsigned long long)m0 | ((unsigned long long)m1 << 32);

    float bin[4], bun[4]; int bix[4];
#pragma unroll
    for (int k = 0; k < 4; k++) { bin[k] = 0.0f; bun[k] = 1.0f; bix[k] = 0; }

    while (mask) {
        int g = __ffsll((long long)mask) - 1;
        mask &= mask - 1;
        float x1 = sgx1[g], y1 = sgy1[g], x2 = sgx2[g], y2 = sgy2[g];
        float ar = sga[g];
        float ti[4], tu[4];
#pragma unroll
        for (int k = 0; k < 4; k++) {
            float lx = fmaxf(x1, q[k].x), ly = fmaxf(y1, q[k].y);
            float rx = fminf(x2, q[k].z), ry = fminf(y2, q[k].w);
            float w = fmaxf(rx - lx, 0.0f), h = fmaxf(ry - ly, 0.0f);
            float inter = w * h;
            float un = (ar + qa[k]) - inter;
            ti[k] = inter; tu[k] = un;
            if (inter * bun[k] > bin[k] * un) { bin[k] = inter; bun[k] = un; bix[k] = g; }
        }
        // local 4-way merge (cross-mult, keep-self on tie)
        float ri = ti[0], ru = tu[0]; int rp = qi[0];
#pragma unroll
        for (int k = 1; k < 4; k++)
            if (ti[k] * ru > ri * tu[k]) { ri = ti[k]; ru = tu[k]; rp = qi[k]; }
        // collapse to ratio; REDUX-based warp argmax
        float r = __fdividef(ri, ru);
        unsigned rb = __float_as_uint(r);          // r >= 0: bits monotone
        unsigned rmax = __reduce_max_sync(0xFFFFFFFFu, rb);
        if (rmax != 0u) {
            unsigned who = __ballot_sync(0xFFFFFFFFu, rb == rmax);
            int src = __ffs(who) - 1;
            int wp = __shfl_sync(0xFFFFFFFFu, rp, src);
            if (lane == 0) {
                s_r[wid][g] = __uint_as_float(rmax);
                s_ix[wid][g] = wp;
            }
        }
    }

    // per-prior results: packed (idx<<1)|thresh, 4B scatter stores
#pragma unroll
    for (int k = 0; k < 4; k++) {
        int flag = (bin[k] >= 0.35f * bun[k]) ? 1 : 0;
        g_btc[(size_t)b * PP + qi[k]] = (bix[k] << 1) | flag;
    }

    __syncthreads();
    // block merge per g + global atomic merge
    if (tid < GG) {
        float r = s_r[0][tid]; int rp = s_ix[0][tid];
#pragma unroll
        for (int w = 1; w < 8; w++) {
            float orr = s_r[w][tid]; int op = s_ix[w][tid];
            if (orr > r || (orr == r && op < rp)) { r = orr; rp = op; }
        }
        if (rp != 0x7FFFFFFF) {
            unsigned long long key =
                ((unsigned long long)__float_as_uint(r) << 32) |
                (unsigned)(~(unsigned)rp);
            atomicMax(&g_best[b * GG + tid], key);
        }
    }
}

// ---------------- loss_c + inline scatter + pos compaction + hist ----------
// 512 threads, 2 priors/thread, window = 1024 priors, 32 blocks per batch
__global__ void __launch_bounds__(512) k_losses(const float* __restrict__ conf_data,
                                                const float* __restrict__ targets) {
    __shared__ int shist[256];
    __shared__ int s_og[1024];
    __shared__ int s_ov[1024];
    __shared__ int s_av;
    __shared__ int s_cnt;
    int b = blockIdx.y, tid = threadIdx.x;
    int lane = tid & 31;
    if (tid < 256) shist[tid] = 0;
    s_og[tid] = -1; s_og[tid + 512] = -1;
    s_ov[tid] = 0;  s_ov[tid + 512] = 0;
    if (tid == 0) { s_av = 0; s_cnt = 0; }
    __syncthreads();

    int pbase = blockIdx.x * 1024;
    if (tid < GG) {
        unsigned long long key = g_best[b * GG + tid];
        int pg = (int)(~(unsigned)(key & 0xFFFFFFFFull));
        float ratio = __uint_as_float((unsigned)(key >> 32));
        int valid = ratio >= 0.2f ? 1 : 0;
        if (valid) s_av = 1;                     // benign race, same value
        int loc = pg - pbase;
        if (loc >= 0 && loc < 1024) {
            atomicMax(&s_og[loc], tid);          // last-wins: highest g
            if (valid) atomicOr(&s_ov[loc], 1);
        }
    }
    __syncthreads();

    int av = s_av;
    size_t segbase = ((size_t)b * 32 + blockIdx.x) * 1024;

    // two independent prior chains for MLP
#pragma unroll
    for (int half = 0; half < 2; half++) {
        int loc = tid + half * 512;
        int p = pbase + loc;
        size_t o = (size_t)b * PP + p;
        int packed = g_btc[o];
        int g = packed >> 1;
        int flag = packed & 1;
        if (s_og[loc] >= 0) {
            g = s_og[loc];
            flag |= s_ov[loc];
            g_btc[o] = (g << 1) | flag;          // write-back for tail pos path
        }

        int conf = 0;
        if (av && flag)
            conf = (int)__ldg(&targets[((size_t)b * GG + g) * 15 + 14]);

        const float* cd = conf_data + o * 3;
        float c0 = cd[0], c1 = cd[1], c2 = cd[2];
        float mx = fmaxf(c0, fmaxf(c1, c2));
        float lse = mx + __logf(__expf(c0 - mx) + __expf(c1 - mx) + __expf(c2 - mx));
        float gathered = (conf == 0) ? c0 : ((conf == 1) ? c1 : c2);
        float lcv = lse - gathered;
        bool pos = conf > 0;
        float stored = pos ? 0.0f : lcv;
        g_lossc[o] = stored;

        // contention-free histogram: match_any aggregation, leader adds popc
        unsigned bv = __float_as_uint(stored) >> 24;
        unsigned hm = __match_any_sync(0xFFFFFFFFu, bv);
        if ((hm & ((1u << lane) - 1)) == 0u)     // lowest lane in group
            atomicAdd(&shist[bv], __popc(hm));

        unsigned m = __ballot_sync(0xFFFFFFFFu, pos);
        int np = __popc(m);
        if (np) {
            int base = 0;
            if (lane == 0) base = atomicAdd(&s_cnt, np);
            base = __shfl_sync(0xFFFFFFFFu, base, 0);
            if (pos)
                g_poslist[segbase + base + __popc(m & ((1u << lane) - 1))] = p;
        }
    }
    __syncthreads();

    if (tid < 256 && shist[tid]) atomicAdd(&g_hist1[b * 256 + tid], shist[tid]);
    if (tid == 0) {
        int c = s_cnt;
        g_segcnt[b * 32 + blockIdx.x] = c;
        if (c) {
            atomicAdd(&g_numpos[b], c);
            atomicAdd(&g_tp, c);
        }
    }
}

// ---------------- fused tail: topk (0-63) + pos (64-127) + final ------------
#define TKT 1024
__global__ void __launch_bounds__(TKT) k_tail(const float* __restrict__ loc_data,
                                              const float* __restrict__ conf_data,
                                              const float* __restrict__ landm_data,
                                              const float* __restrict__ priors,
                                              const float* __restrict__ targets,
                                              float* __restrict__ out) {
    int tid = threadIdx.x, lane = tid & 31, wid = tid >> 5;

    if (blockIdx.x >= 64) {
        // ---- pos path: one segment per warp (2048 warps / 2048 segments) ----
        int seg = (blockIdx.x - 64) * 32 + wid;
        int cnt = g_segcnt[seg];
        int b = seg >> 5;
        size_t segbase = (size_t)seg * 1024;
        double dl = 0.0, dlm = 0.0, dcp = 0.0;
        for (int i = lane; i < cnt; i += 32) {
            int p = g_poslist[segbase + i];
            size_t o = (size_t)b * PP + p;
            int g = g_btc[o] >> 1;
            const float* t = targets + ((size_t)b * GG + g) * 15;
            int conf = (int)t[14];

            const float* cd = conf_data + o * 3;
            float c0 = cd[0], c1 = cd[1], c2 = cd[2];
            float mx = fmaxf(c0, fmaxf(c1, c2));
            float lse = mx + __logf(__expf(c0 - mx) + __expf(c1 - mx) + __expf(c2 - mx));
            dcp += (double)(lse - ((conf == 1) ? c1 : c2));

            float4 pr = ((const float4*)priors)[p];
            float dwx = 0.1f * pr.z, dwy = 0.1f * pr.w;
            float m0 = t[0], m1 = t[1], m2 = t[2], m3 = t[3];
            float gcx = ((m0 + m2) * 0.5f - pr.x) / dwx;
            float gcy = ((m1 + m3) * 0.5f - pr.y) / dwy;
            float gw2 = __logf((m2 - m0) / pr.z) * 5.0f;
            float gh2 = __logf((m3 - m1) / pr.w) * 5.0f;
            const float* ld = loc_data + o * 4;
            dl += (double)(sl1(ld[0] - gcx) + sl1(ld[1] - gcy) +
                           sl1(ld[2] - gw2) + sl1(ld[3] - gh2));

            const float* lt = t + 4;
            const float* lm = landm_data + o * 10;
            int nd = (conf == 1) ? 10 : 4;
            float s = 0.0f;
            for (int j = 0; j < nd; j += 2) {
                float lx = (lt[j] - pr.x) / dwx;
                float ly = (lt[j + 1] - pr.y) / dwy;
                s += sl1(lm[j] - lx) + sl1(lm[j + 1] - ly);
            }
            dlm += (double)s;
        }
#pragma unroll
        for (int off = 16; off > 0; off >>= 1) {
            dl  += __shfl_down_sync(0xFFFFFFFFu, dl, off);
            dlm += __shfl_down_sync(0xFFFFFFFFu, dlm, off);
            dcp += __shfl_down_sync(0xFFFFFFFFu, dcp, off);
        }
        __shared__ double sdp[3][32];
        if (lane == 0) { sdp[0][wid] = dl; sdp[1][wid] = dlm; sdp[2][wid] = dcp; }
        __syncthreads();
        if (tid == 0) {
            double a = 0, b2 = 0, c = 0;
#pragma unroll
            for (int w = 0; w < 32; w++) { a += sdp[0][w]; b2 += sdp[1][w]; c += sdp[2][w]; }
            if (a != 0.0 || b2 != 0.0 || c != 0.0) {
                atomicAdd(&g_acc[0], a);
                atomicAdd(&g_acc[1], b2);
                atomicAdd(&g_acc[2], c);
            }
        }
    } else {
        // ---- topk path ----
        int b = blockIdx.x;
        int np = g_numpos[b];
        long long kk = 7LL * np;
        if (kk > PP - 1) kk = PP - 1;
        if (kk > 0) {
            int k = (int)kk;
            const float* v = g_lossc + (size_t)b * PP;

            __shared__ int shist[4096];
            __shared__ int swtot[32];
            __shared__ unsigned s_prefix;
            __shared__ int s_krem;

            int krem = k;
            unsigned prefix;

            // pass 1: top byte from precomputed g_hist1
            {
                int cnt = (tid < 256) ? g_hist1[b * 256 + tid] : 0;
                int s = cnt;
#pragma unroll
                for (int off = 1; off < 32; off <<= 1) {
                    int o2 = __shfl_down_sync(0xFFFFFFFFu, s, off);
                    if (lane + off < 32) s += o2;
                }
                if (lane == 0) swtot[wid] = s;
                __syncthreads();
                if (tid < 256) {
                    int above = 0;
#pragma unroll
                    for (int w = 0; w < 8; w++)
                        if (w > wid) above += swtot[w];
                    int suffix = s + above;
                    if (suffix >= krem && suffix - cnt < krem) {
                        s_prefix = (unsigned)tid << 24;
                        s_krem = krem - (suffix - cnt);
                    }
                }
                __syncthreads();
                prefix = s_prefix;
                krem = s_krem;
                __syncthreads();
            }

            // pass 2: bits 23..12
            for (int i = tid; i < 4096; i += TKT) shist[i] = 0;
            __syncthreads();
#pragma unroll 4
            for (int i = tid; i < PP; i += TKT) {
                unsigned u = __float_as_uint(v[i]);
                if ((u & 0xFF000000u) == prefix)
                    atomicAdd(&shist[(u >> 12) & 0xFFFu], 1);
            }
            __syncthreads();
            {
                int b0 = tid * 4;
                int c0 = shist[b0], c1 = shist[b0 + 1], c2 = shist[b0 + 2], c3 = shist[b0 + 3];
                int cnt = c0 + c1 + c2 + c3;
                int s = cnt;
#pragma unroll
                for (int off = 1; off < 32; off <<= 1) {
                    int o2 = __shfl_down_sync(0xFFFFFFFFu, s, off);
                    if (lane + off < 32) s += o2;
                }
                if (lane == 0) swtot[wid] = s;
                __syncthreads();
                int above = 0;
#pragma unroll
                for (int w = 0; w < 32; w++)
                    if (w > wid) above += swtot[w];
                int suffix = s + above;
                int cum = suffix - cnt;
                if (cum < krem && suffix >= krem) {
                    int bin, c;
                    if (cum + c3 >= krem)                { bin = b0 + 3; c = cum; }
                    else if (cum + c3 + c2 >= krem)      { bin = b0 + 2; c = cum + c3; }
                    else if (cum + c3 + c2 + c1 >= krem) { bin = b0 + 1; c = cum + c3 + c2; }
                    else                                 { bin = b0;     c = cum + c3 + c2 + c1; }
                    s_prefix = prefix | ((unsigned)bin << 12);
                    s_krem = krem - c;
                }
                __syncthreads();
                prefix = s_prefix;
                krem = s_krem;
                __syncthreads();
            }

            // pass 3: bits 11..0
            for (int i = tid; i < 4096; i += TKT) shist[i] = 0;
            __syncthreads();
#pragma unroll 4
            for (int i = tid; i < PP; i += TKT) {
                unsigned u = __float_as_uint(v[i]);
                if ((u & 0xFFFFF000u) == prefix)
                    atomicAdd(&shist[u & 0xFFFu], 1);
            }
            __syncthreads();
            {
                int b0 = tid * 4;
                int c0 = shist[b0], c1 = shist[b0 + 1], c2 = shist[b0 + 2], c3 = shist[b0 + 3];
                int cnt = c0 + c1 + c2 + c3;
                int s = cnt;
#pragma unroll
                for (int off = 1; off < 32; off <<= 1) {
                    int o2 = __shfl_down_sync(0xFFFFFFFFu, s, off);
                    if (lane + off < 32) s += o2;
                }
                if (lane == 0) swtot[wid] = s;
                __syncthreads();
                int above = 0;
#pragma unroll
                for (int w = 0; w < 32; w++)
                    if (w > wid) above += swtot[w];
                int suffix = s + above;
                int cum = suffix - cnt;
                if (cum < krem && suffix >= krem) {
                    int bin;
                    if (cum + c3 >= krem)                bin = b0 + 3;
                    else if (cum + c3 + c2 >= krem)      bin = b0 + 2;
                    else if (cum + c3 + c2 + c1 >= krem) bin = b0 + 1;
                    else                                 bin = b0;
                    s_prefix = prefix | (unsigned)bin;
                }
                __syncthreads();
                prefix = s_prefix;
                __syncthreads();
            }

            // final: sum strictly above threshold + tie fill
            float t = __uint_as_float(prefix);
            double s = 0.0;
            int c = 0;
#pragma unroll 4
            for (int i = tid; i < PP; i += TKT) {
                float x = v[i];
                if (x > t) { s += (double)x; c++; }
            }
            for (int off = 16; off > 0; off >>= 1) {
                s += __shfl_down_sync(0xFFFFFFFFu, s, off);
                c += __shfl_down_sync(0xFFFFFFFFu, c, off);
            }
            __shared__ double sd[32];
            __shared__ int sc[32];
            if (lane == 0) { sd[wid] = s; sc[wid] = c; }
            __syncthreads();
            if (tid == 0) {
                double S = 0.0;
                int C = 0;
                for (int w = 0; w < 32; w++) { S += sd[w]; C += sc[w]; }
                double res = S + (double)(k - C) * (double)t;
                atomicAdd(&g_topk, res);
            }
        }
    }

    // ---- done-counter: last block writes outputs ----
    if (tid == 0) {
        __threadfence();
        int prev = atomicAdd(&g_done, 1);
        if (prev == 127) {
            __threadfence();
            int tp = g_tp;
            double N = tp > 0 ? (double)tp : 1.0;
            out[0] = (float)(g_acc[0] / N);
            out[1] = (float)((g_acc[2] + g_topk) / N);
            out[2] = (float)(g_acc[1] / N);
        }
    }
}

// ---------------- launch ----------------
extern "C" void kernel_launch(void* const* d_in, const int* in_sizes, int n_in,
                              void* d_out, int out_size) {
    const float *loc = nullptr, *conf = nullptr, *landm = nullptr;
    const float *priors = nullptr, *targets = nullptr;
    for (int i = 0; i < n_in; i++) {
        long long s = in_sizes[i];
        if (s == (long long)BB * PP * 4)       loc     = (const float*)d_in[i];
        else if (s == (long long)BB * PP * 3)  conf    = (const float*)d_in[i];
        else if (s == (long long)BB * PP * 10) landm   = (const float*)d_in[i];
        else if (s == (long long)PP * 4)       priors  = (const float*)d_in[i];
        else if (s == (long long)BB * GG * 15) targets = (const float*)d_in[i];
    }

    k_cell<<<128, 256>>>(priors);
    k_ssort<<<128, 256>>>(priors);
    k_match<<<dim3(PP / 1024, BB), 256>>>(targets);
    k_losses<<<dim3(32, BB), 512>>>(conf, targets);
    k_tail<<<128, TKT>>>(loc, conf, landm, priors, targets, (float*)d_out);
}